// round 2
// baseline (speedup 1.0000x reference)
#include <cuda_runtime.h>
#include <cuda_bf16.h>
#include <math.h>

typedef unsigned int u32;
typedef unsigned long long u64;

// ---------------- problem constants ----------------
#define NPIX    2500
#define HPAD    52
#define QPAD    2704          // 52*52
#define NCH     512
#define KTOT    4608          // 512*9
#define NA      35
#define NANCH   87500         // 2500*35
#define PRE_NMS 6000
#define POST_NMS 300
#define NW      94            // ceil(6000/64)

// output layout (float32, concatenated tuple)
#define OFF_LOCS    0
#define OFF_SCORES  700000
#define OFF_ROIS    1050000
#define OFF_RIDX    1052400
#define OFF_RVALID  1053000
#define OFF_ANCH    1053600

// ---------------- device scratch (no allocation allowed) ----------------
__device__ __align__(16) float g_pad[2 * NCH * QPAD];
__device__ __align__(16) float g_h[2 * NCH * NPIX];
__device__ __align__(16) float g_scores[2 * 70 * NPIX];
__device__ __align__(16) float g_locs[2 * 140 * NPIX];
__device__ float4 g_anchors[NANCH];
__device__ u64    g_keys[2 * NANCH];
__device__ float4 g_boxes[2 * NANCH];
__device__ u64    g_kth[2];
__device__ int    g_cnt[2];
__device__ u64    g_top[2 * PRE_NMS];
__device__ float4 g_nmsbox[2 * PRE_NMS];
__device__ u64    g_mask[(size_t)2 * PRE_NMS * NW];
__device__ u64    g_validb[2 * NW];
__device__ u64    g_keepw[2 * NW];

// ---------------- 1: pad input (zero border) ----------------
__global__ void pad_kernel(const float* __restrict__ feat)
{
    int idx = blockIdx.x * blockDim.x + threadIdx.x;
    if (idx >= 2 * NCH * QPAD) return;
    int plane = idx / QPAD;
    int q = idx - plane * QPAD;
    int i = q / HPAD, j = q - i * HPAD;
    float v = 0.f;
    if (i >= 1 && i <= 50 && j >= 1 && j <= 50)
        v = feat[(size_t)plane * NPIX + (i - 1) * 50 + (j - 1)];
    g_pad[idx] = v;
}

// ---------------- 2: anchors (exact numpy semantics: fp64 base, fp32 add, clip) ----------------
__global__ void anchors_kernel(float* __restrict__ out)
{
    int idx = blockIdx.x * blockDim.x + threadIdx.x;
    if (idx >= NANCH) return;
    int p = idx / NA, a = idx - p * NA;
    int ri = a / 5, si = a - ri * 5;
    const double RAT[7] = {0.5, 0.66, 0.75, 1.0, 1.33, 1.5, 2.0};
    const double SCL[5] = {2.0, 4.0, 8.0, 16.0, 32.0};
    double hh = 16.0 * SCL[si] * sqrt(RAT[ri]);
    double ww = 16.0 * SCL[si] * sqrt(1.0 / RAT[ri]);
    float a0 = (float)(8.0 - hh / 2.0);
    float a1 = (float)(8.0 - ww / 2.0);
    float a2 = (float)(8.0 + hh / 2.0);
    float a3 = (float)(8.0 + ww / 2.0);
    int iy = p / 50, jx = p - iy * 50;
    float sy = (float)(iy * 16), sx = (float)(jx * 16);
    float y1 = fminf(fmaxf(a0 + sy, 0.f), 799.f);
    float x1 = fminf(fmaxf(a1 + sx, 0.f), 799.f);
    float y2 = fminf(fmaxf(a2 + sy, 0.f), 799.f);
    float x2 = fminf(fmaxf(a3 + sx, 0.f), 799.f);
    g_anchors[idx] = make_float4(y1, x1, y2, x2);
    size_t o = OFF_ANCH + (size_t)idx * 4;
    out[o + 0] = y1; out[o + 1] = x1; out[o + 2] = y2; out[o + 3] = x2;
}

// ---------------- 3: conv3x3 + bias + relu as implicit GEMM ----------------
// C[co][p] = sum_{k=ci*9+r} W[co][k] * pad[ci][(i+dy)*52 + j+dx]
// tile 128co x 128pix, 256 threads, 8x8 micro-tile, KB=8
__global__ void __launch_bounds__(256, 2)
conv3x3_kernel(const float* __restrict__ W, const float* __restrict__ bias)
{
    const int bx = blockIdx.x;     // pixel tile (20)
    const int by = blockIdx.y;     // co tile (4)
    const int bz = blockIdx.z;     // batch
    const int tid = threadIdx.x;
    const int n0 = bx * 128;
    const int m0 = by * 128;
    __shared__ __align__(16) float As[8][128];
    __shared__ __align__(16) float Bs[8][128];
    const int tm = tid >> 4;       // 0..15
    const int tn = tid & 15;       // 0..15
    float acc[8][8];
#pragma unroll
    for (int u = 0; u < 8; u++)
#pragma unroll
        for (int v = 0; v < 8; v++) acc[u][v] = 0.f;

    const int a_co = tid >> 1;             // 0..127
    const int a_kq = (tid & 1) * 4;        // 0 / 4
    const int b_kk = tid >> 5;             // 0..7
    const int b_pl = (tid & 31) * 4;       // 0..124
    const float* padB = g_pad + (size_t)bz * NCH * QPAD;

    for (int k0 = 0; k0 < KTOT; k0 += 8) {
        // global loads into registers
        float4 av4 = *(const float4*)&W[(size_t)(m0 + a_co) * KTOT + k0 + a_kq];
        int k = k0 + b_kk;
        int ci = k / 9;
        int r = k - ci * 9;
        int dy = r / 3, dx = r - dy * 3;
        const float* pp = padB + (size_t)ci * QPAD;
        float bv[4];
#pragma unroll
        for (int q = 0; q < 4; q++) {
            int p = n0 + b_pl + q;
            if (p < NPIX) {
                int i = p / 50, j = p - 50 * i;
                bv[q] = pp[(i + dy) * HPAD + (j + dx)];
            } else bv[q] = 0.f;
        }
        __syncthreads();
        As[a_kq + 0][a_co] = av4.x;
        As[a_kq + 1][a_co] = av4.y;
        As[a_kq + 2][a_co] = av4.z;
        As[a_kq + 3][a_co] = av4.w;
        Bs[b_kk][b_pl + 0] = bv[0];
        Bs[b_kk][b_pl + 1] = bv[1];
        Bs[b_kk][b_pl + 2] = bv[2];
        Bs[b_kk][b_pl + 3] = bv[3];
        __syncthreads();
#pragma unroll
        for (int kk = 0; kk < 8; kk++) {
            float4 aa0 = *(const float4*)&As[kk][tm * 8];
            float4 aa1 = *(const float4*)&As[kk][tm * 8 + 4];
            float4 bb0 = *(const float4*)&Bs[kk][tn * 8];
            float4 bb1 = *(const float4*)&Bs[kk][tn * 8 + 4];
            float aarr[8] = {aa0.x, aa0.y, aa0.z, aa0.w, aa1.x, aa1.y, aa1.z, aa1.w};
            float barr[8] = {bb0.x, bb0.y, bb0.z, bb0.w, bb1.x, bb1.y, bb1.z, bb1.w};
#pragma unroll
            for (int u = 0; u < 8; u++)
#pragma unroll
                for (int v = 0; v < 8; v++)
                    acc[u][v] = fmaf(aarr[u], barr[v], acc[u][v]);
        }
    }
    // epilogue: bias + relu
#pragma unroll
    for (int u = 0; u < 8; u++) {
        int co = m0 + tm * 8 + u;
        float bb = bias[co];
        float* outrow = g_h + ((size_t)bz * NCH + co) * NPIX;
#pragma unroll
        for (int v = 0; v < 8; v++) {
            int p = n0 + tn * 8 + v;
            if (p < NPIX) outrow[p] = fmaxf(acc[u][v] + bb, 0.f);
        }
    }
}

// ---------------- 4: 1x1 conv GEMM: out[b][co][p] = sum_ci W[co][ci]*h[b][ci][p] + bias ----------------
// tile 64co x 64pix, 256 threads, 4x4 micro, KB=16. mode 0 -> g_scores (M=70), 1 -> g_locs (M=140)
__global__ void __launch_bounds__(256)
gemm1x1_kernel(const float* __restrict__ W, const float* __restrict__ bias, int M, int mode)
{
    const int bx = blockIdx.x;     // pixel tile (40)
    const int by = blockIdx.y;     // co tile
    const int bz = blockIdx.z;     // batch
    const int tid = threadIdx.x;
    const int n0 = bx * 64;
    const int m0 = by * 64;
    __shared__ __align__(16) float As[16][64];
    __shared__ __align__(16) float Bs[16][64];
    const int tm = tid >> 4, tn = tid & 15;
    float acc[4][4];
#pragma unroll
    for (int u = 0; u < 4; u++)
#pragma unroll
        for (int v = 0; v < 4; v++) acc[u][v] = 0.f;

    const int a_co = tid >> 2;           // 0..63
    const int a_kq = (tid & 3) * 4;      // 0,4,8,12
    const int b_kk = tid >> 4;           // 0..15
    const int b_p0 = (tid & 15) * 4;     // 0..60
    const float* Hb = g_h + (size_t)bz * NCH * NPIX;

    for (int k0 = 0; k0 < NCH; k0 += 16) {
        int co = m0 + a_co;
        float4 av = make_float4(0.f, 0.f, 0.f, 0.f);
        if (co < M) av = *(const float4*)&W[(size_t)co * NCH + k0 + a_kq];
        int p0 = n0 + b_p0;
        float4 bv = make_float4(0.f, 0.f, 0.f, 0.f);
        if (p0 < NPIX) bv = *(const float4*)&Hb[(size_t)(k0 + b_kk) * NPIX + p0];
        __syncthreads();
        As[a_kq + 0][a_co] = av.x;
        As[a_kq + 1][a_co] = av.y;
        As[a_kq + 2][a_co] = av.z;
        As[a_kq + 3][a_co] = av.w;
        *(float4*)&Bs[b_kk][b_p0] = bv;
        __syncthreads();
#pragma unroll
        for (int kk = 0; kk < 16; kk++) {
            float4 aa = *(const float4*)&As[kk][tm * 4];
            float4 bb = *(const float4*)&Bs[kk][tn * 4];
            float aarr[4] = {aa.x, aa.y, aa.z, aa.w};
            float barr[4] = {bb.x, bb.y, bb.z, bb.w};
#pragma unroll
            for (int u = 0; u < 4; u++)
#pragma unroll
                for (int v = 0; v < 4; v++)
                    acc[u][v] = fmaf(aarr[u], barr[v], acc[u][v]);
        }
    }
    float* outbase = mode ? g_locs : g_scores;
#pragma unroll
    for (int u = 0; u < 4; u++) {
        int co = m0 + tm * 4 + u;
        if (co >= M) continue;
        float bb = bias[co];
        float* orow = outbase + ((size_t)bz * M + co) * NPIX;
#pragma unroll
        for (int v = 0; v < 4; v++) {
            int p = n0 + tn * 4 + v;
            if (p < NPIX) orow[p] = acc[u][v] + bb;
        }
    }
}

// ---------------- 5: decode boxes, softmax fg, keys; write pred_locs/pred_scores ----------------
__global__ void decode_kernel(float* __restrict__ out)
{
    int idx = blockIdx.x * blockDim.x + threadIdx.x;
    if (idx >= 2 * NANCH) return;
    int b = idx / NANCH;
    int pa = idx - b * NANCH;
    int p = pa / NA;
    int a = pa - p * NA;

    const float* sc = g_scores + (size_t)b * 70 * NPIX;
    float x0 = sc[(a * 2 + 0) * NPIX + p];
    float x1 = sc[(a * 2 + 1) * NPIX + p];
    size_t so = OFF_SCORES + (size_t)b * 175000 + (size_t)pa * 2;
    out[so + 0] = x0;
    out[so + 1] = x1;
    float mx = fmaxf(x0, x1);
    float e0 = expf(x0 - mx), e1 = expf(x1 - mx);
    float fg = e1 / (e0 + e1);

    const float* lc = g_locs + (size_t)b * 140 * NPIX;
    float dy  = lc[(a * 4 + 0) * NPIX + p];
    float dx_ = lc[(a * 4 + 1) * NPIX + p];
    float dh  = lc[(a * 4 + 2) * NPIX + p];
    float dw  = lc[(a * 4 + 3) * NPIX + p];
    size_t lo = OFF_LOCS + (size_t)b * 350000 + (size_t)pa * 4;
    out[lo + 0] = dy; out[lo + 1] = dx_; out[lo + 2] = dh; out[lo + 3] = dw;

    float4 an = g_anchors[pa];
    float ah = an.z - an.x, aw = an.w - an.y;
    float acy = an.x + 0.5f * ah, acx = an.y + 0.5f * aw;
    float cy = dy * ah + acy, cx = dx_ * aw + acx;
    float hh = expf(dh) * ah, ww = expf(dw) * aw;
    float y1 = cy - 0.5f * hh, x1b = cx - 0.5f * ww;
    float y2 = cy + 0.5f * hh, x2b = cx + 0.5f * ww;
    y1 = fminf(fmaxf(y1, 0.f), 800.f);
    x1b = fminf(fmaxf(x1b, 0.f), 800.f);
    y2 = fminf(fmaxf(y2, 0.f), 800.f);
    x2b = fminf(fmaxf(x2b, 0.f), 800.f);
    float hs = y2 - y1, ws = x2b - x1b;
    bool valid = (hs >= 16.f) && (ws >= 16.f);
    float s = valid ? fg : -__int_as_float(0x7f800000);

    u32 sb = __float_as_uint(s);
    u32 mm = (sb & 0x80000000u) ? ~sb : (sb | 0x80000000u);  // ascending-order map
    u64 key = ((u64)(~mm) << 32) | (u32)pa;                  // ascending key = best first
    g_keys[idx] = key;
    g_boxes[idx] = make_float4(y1, x1b, y2, x2b);
}

// ---------------- 6: zero counters ----------------
__global__ void zero_kernel()
{
    int t = threadIdx.x;
    if (t < 2) g_cnt[t] = 0;
    for (int i = t; i < 2 * NW; i += 256) g_validb[i] = 0ull;
}

// ---------------- 7: exact rank-5999 key via 8-pass MSB radix select ----------------
__global__ void select_kth_kernel()
{
    int b = blockIdx.x;
    int tid = threadIdx.x;
    int lane = tid & 31;
    __shared__ u32 hist[256];
    __shared__ u64 sprefix;
    __shared__ u32 srank;
    if (tid == 0) { sprefix = 0ull; srank = PRE_NMS - 1; }
    const u64* keys = g_keys + (size_t)b * NANCH;
    for (int d = 7; d >= 0; d--) {
        __syncthreads();
        for (int i = tid; i < 256; i += 1024) hist[i] = 0;
        __syncthreads();
        u64 pref = sprefix;
        int hishift = 8 * (d + 1);
        for (int base = 0; base < NANCH; base += 1024) {
            int i = base + tid;
            bool ok = (i < NANCH);
            u32 bin = 0;
            if (ok) {
                u64 k = keys[i];
                if (d < 7) ok = (((k ^ pref) >> hishift) == 0);
                bin = (u32)(k >> (8 * d)) & 0xffu;
            }
            unsigned act = __ballot_sync(0xffffffffu, ok);
            if (ok) {
                unsigned grp = __match_any_sync(act, bin);
                int leader = __ffs(grp) - 1;
                if (lane == leader) atomicAdd(&hist[bin], (u32)__popc(grp));
            }
        }
        __syncthreads();
        if (tid == 0) {
            u32 run = 0, r = srank;
            for (int bin = 0; bin < 256; bin++) {
                u32 c = hist[bin];
                if (run + c > r) {
                    sprefix = pref | ((u64)bin << (8 * d));
                    srank = r - run;
                    break;
                }
                run += c;
            }
        }
    }
    __syncthreads();
    if (tid == 0) g_kth[b] = sprefix;
}

// ---------------- 8: compact keys <= kth (exactly 6000, keys unique) ----------------
__global__ void compact_kernel()
{
    int idx = blockIdx.x * blockDim.x + threadIdx.x;
    if (idx >= 2 * NANCH) return;
    int b = idx / NANCH;
    u64 k = g_keys[idx];
    if (k <= g_kth[b]) {
        int pos = atomicAdd(&g_cnt[b], 1);
        g_top[(size_t)b * PRE_NMS + pos] = k;
    }
}

// ---------------- 9: bitonic sort 8192 (6000 keys + pad) per batch ----------------
__global__ void sort_kernel()
{
    extern __shared__ u64 s[];
    int b = blockIdx.x;
    int tid = threadIdx.x;
    for (int i = tid; i < 8192; i += 1024)
        s[i] = (i < PRE_NMS) ? g_top[(size_t)b * PRE_NMS + i] : ~0ull;
    __syncthreads();
    for (int k = 2; k <= 8192; k <<= 1) {
        for (int j = k >> 1; j > 0; j >>= 1) {
            for (int t = tid; t < 8192; t += 1024) {
                int ixj = t ^ j;
                if (ixj > t) {
                    bool up = ((t & k) == 0);
                    u64 x = s[t], y = s[ixj];
                    if ((x > y) == up) { s[t] = y; s[ixj] = x; }
                }
            }
            __syncthreads();
        }
    }
    for (int i = tid; i < PRE_NMS; i += 1024)
        g_top[(size_t)b * PRE_NMS + i] = s[i];
}

// ---------------- 10: gather sorted boxes + valid bits ----------------
__global__ void gather_kernel()
{
    int idx = blockIdx.x * blockDim.x + threadIdx.x;
    if (idx >= 2 * PRE_NMS) return;
    int b = idx / PRE_NMS;
    int j = idx - b * PRE_NMS;
    u64 k = g_top[idx];
    u32 ai = (u32)(k & 0xffffffffull);
    g_nmsbox[idx] = g_boxes[(size_t)b * NANCH + ai];
    bool valid = ((u32)(k >> 32)) != 0xFF800000u;   // -inf score marker
    if (valid) atomicOr(&g_validb[b * NW + (j >> 6)], 1ull << (j & 63));
}

// ---------------- 11: NMS IoU bitmask ----------------
__global__ void nms_mask_kernel()
{
    int cb = blockIdx.x, rb = blockIdx.y, b = blockIdx.z;
    int tid = threadIdx.x;
    __shared__ float4 cbox[64];
    int j = cb * 64 + tid;
    cbox[tid] = (j < PRE_NMS) ? g_nmsbox[(size_t)b * PRE_NMS + j]
                              : make_float4(0.f, 0.f, 0.f, 0.f);
    __syncthreads();
    int i = rb * 64 + tid;
    if (i >= PRE_NMS) return;
    float4 rr = g_nmsbox[(size_t)b * PRE_NMS + i];
    float areai = (rr.z - rr.x) * (rr.w - rr.y);
    u64 bits = 0ull;
#pragma unroll 4
    for (int c = 0; c < 64; c++) {
        int jj = cb * 64 + c;
        if (jj <= i || jj >= PRE_NMS) continue;
        float4 cc = cbox[c];
        float ty = fmaxf(rr.x, cc.x), tx = fmaxf(rr.y, cc.y);
        float by = fminf(rr.z, cc.z), bx2 = fminf(rr.w, cc.w);
        float wy = fmaxf(by - ty, 0.f), wx = fmaxf(bx2 - tx, 0.f);
        float inter = wy * wx;
        float areaj = (cc.z - cc.x) * (cc.w - cc.y);
        float iou = inter / (areai + areaj - inter + 1e-9f);
        if (iou > 0.7f) bits |= 1ull << c;
    }
    g_mask[((size_t)b * PRE_NMS + i) * NW + cb] = bits;
}

// ---------------- 12: sequential NMS reduction, one warp per batch ----------------
__global__ void nms_reduce_kernel()
{
    int b = threadIdx.x >> 5;
    int lane = threadIdx.x & 31;
    u64 remv[3] = {0ull, 0ull, 0ull};
    u64 keep[3] = {0ull, 0ull, 0ull};
    u64 vw[3];
#pragma unroll
    for (int s2 = 0; s2 < 3; s2++) {
        int w = lane + s2 * 32;
        vw[s2] = (w < NW) ? g_validb[b * NW + w] : 0ull;
    }
    for (int w = 0; w < NW; w++) {
        int owner = w & 31, slot = w >> 5;
        u64 cur = 0ull;
        if (lane == owner) cur = vw[slot] & ~remv[slot];
        cur = __shfl_sync(0xffffffffu, cur, owner);
        while (cur) {
            int bit = __ffsll((long long)cur) - 1;
            int i = w * 64 + bit;
            if (lane == owner) keep[slot] |= (1ull << bit);
            const u64* row = &g_mask[((size_t)b * PRE_NMS + i) * NW];
            u64 m0 = row[lane];
            u64 m1 = (lane + 32 < NW) ? row[lane + 32] : 0ull;
            u64 m2 = (lane + 64 < NW) ? row[lane + 64] : 0ull;
            remv[0] |= m0; remv[1] |= m1; remv[2] |= m2;
            u64 mw = (slot == 0) ? m0 : (slot == 1) ? m1 : m2;
            mw = __shfl_sync(0xffffffffu, mw, owner);
            cur = (cur & ~mw) & ~(1ull << bit);
        }
    }
#pragma unroll
    for (int s2 = 0; s2 < 3; s2++) {
        int w = lane + s2 * 32;
        if (w < NW) g_keepw[b * NW + w] = keep[s2];
    }
}

// ---------------- 13: finalize rois / roi_indices / roi_valid ----------------
__global__ void finalize_kernel(float* __restrict__ out)
{
    int b = blockIdx.x;
    int tid = threadIdx.x;   // 128 threads
    __shared__ u64 kw[NW];
    __shared__ u32 kscan[NW];
    __shared__ u32 ktot;
    __shared__ int sel[POST_NMS];
    for (int w = tid; w < NW; w += 128) kw[w] = g_keepw[b * NW + w];
    __syncthreads();
    if (tid == 0) {
        u32 r = 0;
        for (int w = 0; w < NW; w++) { kscan[w] = r; r += (u32)__popcll(kw[w]); }
        ktot = r;
    }
    __syncthreads();
    u32 ktot_l = ktot;
    for (int w = tid; w < NW; w += 128) {
        u64 bits = kw[w];
        u32 base = kscan[w];
        u64 t = bits;
        while (t) {
            int bit = __ffsll((long long)t) - 1;
            t &= t - 1;
            if (base < POST_NMS) sel[base] = w * 64 + bit;
            base++;
        }
        u64 lim = (w == NW - 1) ? ((1ull << 48) - 1ull) : ~0ull;  // 6000 = 93*64+48
        u64 nt = (~bits) & lim;
        while (nt) {
            int bit = __ffsll((long long)nt) - 1;
            nt &= nt - 1;
            int i = w * 64 + bit;
            u64 below = (bit == 0) ? 0ull : ((1ull << bit) - 1ull);
            u32 kept_before = kscan[w] + (u32)__popcll(bits & below);
            u32 slot = ktot_l + (u32)i - kept_before;
            if (slot < POST_NMS) sel[slot] = i;
        }
    }
    __syncthreads();
    for (int s2 = tid; s2 < POST_NMS; s2 += 128) {
        int i = sel[s2];
        int v = (int)((kw[i >> 6] >> (i & 63)) & 1ull);
        float4 bx = v ? g_nmsbox[(size_t)b * PRE_NMS + i] : make_float4(0.f, 0.f, 0.f, 0.f);
        size_t ro = OFF_ROIS + (size_t)b * POST_NMS * 4 + (size_t)s2 * 4;
        out[ro + 0] = bx.x; out[ro + 1] = bx.y; out[ro + 2] = bx.z; out[ro + 3] = bx.w;
        out[OFF_RIDX + (size_t)b * POST_NMS + s2] = (float)b;
        out[OFF_RVALID + (size_t)b * POST_NMS + s2] = (float)v;
    }
}

// ---------------- launch ----------------
extern "C" void kernel_launch(void* const* d_in, const int* in_sizes, int n_in,
                              void* d_out, int out_size)
{
    const float* feat   = (const float*)d_in[0];
    const float* convw  = (const float*)d_in[1];
    const float* convb  = (const float*)d_in[2];
    const float* scorew = (const float*)d_in[3];
    const float* scoreb = (const float*)d_in[4];
    const float* locw   = (const float*)d_in[5];
    const float* locb   = (const float*)d_in[6];
    float* out = (float*)d_out;

    cudaFuncSetAttribute(sort_kernel, cudaFuncAttributeMaxDynamicSharedMemorySize, 65536);

    pad_kernel<<<(2 * NCH * QPAD + 255) / 256, 256>>>(feat);
    anchors_kernel<<<(NANCH + 127) / 128, 128>>>(out);
    conv3x3_kernel<<<dim3(20, 4, 2), 256>>>(convw, convb);
    gemm1x1_kernel<<<dim3(40, 2, 2), 256>>>(scorew, scoreb, 70, 0);
    gemm1x1_kernel<<<dim3(40, 3, 2), 256>>>(locw, locb, 140, 1);
    decode_kernel<<<(2 * NANCH + 255) / 256, 256>>>(out);
    zero_kernel<<<1, 256>>>();
    select_kth_kernel<<<2, 1024>>>();
    compact_kernel<<<(2 * NANCH + 255) / 256, 256>>>();
    sort_kernel<<<2, 1024, 65536>>>();
    gather_kernel<<<(2 * PRE_NMS + 255) / 256, 256>>>();
    nms_mask_kernel<<<dim3(NW, NW, 2), 64>>>();
    nms_reduce_kernel<<<1, 64>>>();
    finalize_kernel<<<2, 128>>>(out);
}

// round 3
// speedup vs baseline: 1.5259x; 1.5259x over previous
#include <cuda_runtime.h>
#include <cuda_bf16.h>
#include <math.h>

typedef unsigned int u32;
typedef unsigned long long u64;

// ---------------- problem constants ----------------
#define NPIX    2500
#define HPAD    52
#define QPAD    2704          // 52*52
#define NCH     512
#define KTOT    4608          // 512*9
#define NA      35
#define NANCH   87500         // 2500*35
#define PRE_NMS 6000
#define POST_NMS 300
#define NW      94            // ceil(6000/64)
#define TOPCAP  8192

// output layout (float32, concatenated tuple)
#define OFF_LOCS    0
#define OFF_SCORES  700000
#define OFF_ROIS    1050000
#define OFF_RIDX    1052400
#define OFF_RVALID  1053000
#define OFF_ANCH    1053600

// ---------------- device scratch (no allocation allowed) ----------------
__device__ __align__(16) float g_pad[2 * NCH * QPAD];
__device__ __align__(16) float g_h[2 * NCH * NPIX];
__device__ __align__(16) float g_scores[2 * 70 * NPIX];
__device__ __align__(16) float g_locs[2 * 140 * NPIX];
__device__ float4 g_anchors[NANCH];
__device__ u64    g_keys[2 * NANCH];
__device__ float4 g_boxes[2 * NANCH];
__device__ int    g_cnt[2];
__device__ u64    g_top[2 * TOPCAP];
__device__ float4 g_nmsbox[2 * PRE_NMS];
__device__ u64    g_mask[(size_t)2 * PRE_NMS * NW];
__device__ u64    g_validb[2 * NW];
__device__ u64    g_keepw[2 * NW];
__device__ u32    g_hist1[2 * 65536];
__device__ u32    g_hist2[2 * 65536];
__device__ u32    g_prefix[2];
__device__ u32    g_rank[2];
__device__ u32    g_thresh[2];

// ---------------- pad input (zero border); half per launch ----------------
__global__ void pad_kernel(const float* __restrict__ feat, int half)
{
    int idx = blockIdx.x * blockDim.x + threadIdx.x + half * (NCH * QPAD);
    if (idx >= (half + 1) * NCH * QPAD) return;
    int plane = idx / QPAD;
    int q = idx - plane * QPAD;
    int i = q / HPAD, j = q - i * HPAD;
    float v = 0.f;
    if (i >= 1 && i <= 50 && j >= 1 && j <= 50)
        v = feat[(size_t)plane * NPIX + (i - 1) * 50 + (j - 1)];
    g_pad[idx] = v;
}

// ---------------- anchors (fp64 base, fp32 add, clip) ----------------
__global__ void anchors_kernel(float* __restrict__ out)
{
    int idx = blockIdx.x * blockDim.x + threadIdx.x;
    if (idx >= NANCH) return;
    int p = idx / NA, a = idx - p * NA;
    int ri = a / 5, si = a - ri * 5;
    const double RAT[7] = {0.5, 0.66, 0.75, 1.0, 1.33, 1.5, 2.0};
    const double SCL[5] = {2.0, 4.0, 8.0, 16.0, 32.0};
    double hh = 16.0 * SCL[si] * sqrt(RAT[ri]);
    double ww = 16.0 * SCL[si] * sqrt(1.0 / RAT[ri]);
    float a0 = (float)(8.0 - hh / 2.0);
    float a1 = (float)(8.0 - ww / 2.0);
    float a2 = (float)(8.0 + hh / 2.0);
    float a3 = (float)(8.0 + ww / 2.0);
    int iy = p / 50, jx = p - iy * 50;
    float sy = (float)(iy * 16), sx = (float)(jx * 16);
    float y1 = fminf(fmaxf(a0 + sy, 0.f), 799.f);
    float x1 = fminf(fmaxf(a1 + sx, 0.f), 799.f);
    float y2 = fminf(fmaxf(a2 + sy, 0.f), 799.f);
    float x2 = fminf(fmaxf(a3 + sx, 0.f), 799.f);
    g_anchors[idx] = make_float4(y1, x1, y2, x2);
    size_t o = OFF_ANCH + (size_t)idx * 4;
    out[o + 0] = y1; out[o + 1] = x1; out[o + 2] = y2; out[o + 3] = x2;
}

// ---------------- conv3x3 + bias + relu as implicit GEMM ----------------
__global__ void __launch_bounds__(256, 2)
conv3x3_kernel(const float* __restrict__ W, const float* __restrict__ bias)
{
    const int bx = blockIdx.x;     // pixel tile (20)
    const int by = blockIdx.y;     // co tile (4)
    const int bz = blockIdx.z;     // batch
    const int tid = threadIdx.x;
    const int n0 = bx * 128;
    const int m0 = by * 128;
    __shared__ __align__(16) float As[8][128];
    __shared__ __align__(16) float Bs[8][128];
    const int tm = tid >> 4;
    const int tn = tid & 15;
    float acc[8][8];
#pragma unroll
    for (int u = 0; u < 8; u++)
#pragma unroll
        for (int v = 0; v < 8; v++) acc[u][v] = 0.f;

    const int a_co = tid >> 1;
    const int a_kq = (tid & 1) * 4;
    const int b_kk = tid >> 5;
    const int b_pl = (tid & 31) * 4;
    const float* padB = g_pad + (size_t)bz * NCH * QPAD;

    for (int k0 = 0; k0 < KTOT; k0 += 8) {
        float4 av4 = *(const float4*)&W[(size_t)(m0 + a_co) * KTOT + k0 + a_kq];
        int k = k0 + b_kk;
        int ci = k / 9;
        int r = k - ci * 9;
        int dy = r / 3, dx = r - dy * 3;
        const float* pp = padB + (size_t)ci * QPAD;
        float bv[4];
#pragma unroll
        for (int q = 0; q < 4; q++) {
            int p = n0 + b_pl + q;
            if (p < NPIX) {
                int i = p / 50, j = p - 50 * i;
                bv[q] = pp[(i + dy) * HPAD + (j + dx)];
            } else bv[q] = 0.f;
        }
        __syncthreads();
        As[a_kq + 0][a_co] = av4.x;
        As[a_kq + 1][a_co] = av4.y;
        As[a_kq + 2][a_co] = av4.z;
        As[a_kq + 3][a_co] = av4.w;
        Bs[b_kk][b_pl + 0] = bv[0];
        Bs[b_kk][b_pl + 1] = bv[1];
        Bs[b_kk][b_pl + 2] = bv[2];
        Bs[b_kk][b_pl + 3] = bv[3];
        __syncthreads();
#pragma unroll
        for (int kk = 0; kk < 8; kk++) {
            float4 aa0 = *(const float4*)&As[kk][tm * 8];
            float4 aa1 = *(const float4*)&As[kk][tm * 8 + 4];
            float4 bb0 = *(const float4*)&Bs[kk][tn * 8];
            float4 bb1 = *(const float4*)&Bs[kk][tn * 8 + 4];
            float aarr[8] = {aa0.x, aa0.y, aa0.z, aa0.w, aa1.x, aa1.y, aa1.z, aa1.w};
            float barr[8] = {bb0.x, bb0.y, bb0.z, bb0.w, bb1.x, bb1.y, bb1.z, bb1.w};
#pragma unroll
            for (int u = 0; u < 8; u++)
#pragma unroll
                for (int v = 0; v < 8; v++)
                    acc[u][v] = fmaf(aarr[u], barr[v], acc[u][v]);
        }
    }
#pragma unroll
    for (int u = 0; u < 8; u++) {
        int co = m0 + tm * 8 + u;
        float bb = bias[co];
        float* outrow = g_h + ((size_t)bz * NCH + co) * NPIX;
#pragma unroll
        for (int v = 0; v < 8; v++) {
            int p = n0 + tn * 8 + v;
            if (p < NPIX) outrow[p] = fmaxf(acc[u][v] + bb, 0.f);
        }
    }
}

// ---------------- 1x1 conv GEMM ----------------
__global__ void __launch_bounds__(256)
gemm1x1_kernel(const float* __restrict__ W, const float* __restrict__ bias, int M, int mode)
{
    const int bx = blockIdx.x;
    const int by = blockIdx.y;
    const int bz = blockIdx.z;
    const int tid = threadIdx.x;
    const int n0 = bx * 64;
    const int m0 = by * 64;
    __shared__ __align__(16) float As[16][64];
    __shared__ __align__(16) float Bs[16][64];
    const int tm = tid >> 4, tn = tid & 15;
    float acc[4][4];
#pragma unroll
    for (int u = 0; u < 4; u++)
#pragma unroll
        for (int v = 0; v < 4; v++) acc[u][v] = 0.f;

    const int a_co = tid >> 2;
    const int a_kq = (tid & 3) * 4;
    const int b_kk = tid >> 4;
    const int b_p0 = (tid & 15) * 4;
    const float* Hb = g_h + (size_t)bz * NCH * NPIX;

    for (int k0 = 0; k0 < NCH; k0 += 16) {
        int co = m0 + a_co;
        float4 av = make_float4(0.f, 0.f, 0.f, 0.f);
        if (co < M) av = *(const float4*)&W[(size_t)co * NCH + k0 + a_kq];
        int p0 = n0 + b_p0;
        float4 bv = make_float4(0.f, 0.f, 0.f, 0.f);
        if (p0 < NPIX) bv = *(const float4*)&Hb[(size_t)(k0 + b_kk) * NPIX + p0];
        __syncthreads();
        As[a_kq + 0][a_co] = av.x;
        As[a_kq + 1][a_co] = av.y;
        As[a_kq + 2][a_co] = av.z;
        As[a_kq + 3][a_co] = av.w;
        *(float4*)&Bs[b_kk][b_p0] = bv;
        __syncthreads();
#pragma unroll
        for (int kk = 0; kk < 16; kk++) {
            float4 aa = *(const float4*)&As[kk][tm * 4];
            float4 bb = *(const float4*)&Bs[kk][tn * 4];
            float aarr[4] = {aa.x, aa.y, aa.z, aa.w};
            float barr[4] = {bb.x, bb.y, bb.z, bb.w};
#pragma unroll
            for (int u = 0; u < 4; u++)
#pragma unroll
                for (int v = 0; v < 4; v++)
                    acc[u][v] = fmaf(aarr[u], barr[v], acc[u][v]);
        }
    }
    float* outbase = mode ? g_locs : g_scores;
#pragma unroll
    for (int u = 0; u < 4; u++) {
        int co = m0 + tm * 4 + u;
        if (co >= M) continue;
        float bb = bias[co];
        float* orow = outbase + ((size_t)bz * M + co) * NPIX;
#pragma unroll
        for (int v = 0; v < 4; v++) {
            int p = n0 + tn * 4 + v;
            if (p < NPIX) orow[p] = acc[u][v] + bb;
        }
    }
}

// ---------------- decode boxes, softmax fg, keys ----------------
__global__ void decode_kernel(float* __restrict__ out)
{
    int idx = blockIdx.x * blockDim.x + threadIdx.x;
    if (idx >= 2 * NANCH) return;
    int b = idx / NANCH;
    int pa = idx - b * NANCH;
    int p = pa / NA;
    int a = pa - p * NA;

    const float* sc = g_scores + (size_t)b * 70 * NPIX;
    float x0 = sc[(a * 2 + 0) * NPIX + p];
    float x1 = sc[(a * 2 + 1) * NPIX + p];
    size_t so = OFF_SCORES + (size_t)b * 175000 + (size_t)pa * 2;
    out[so + 0] = x0;
    out[so + 1] = x1;
    float mx = fmaxf(x0, x1);
    float e0 = expf(x0 - mx), e1 = expf(x1 - mx);
    float fg = e1 / (e0 + e1);

    const float* lc = g_locs + (size_t)b * 140 * NPIX;
    float dy  = lc[(a * 4 + 0) * NPIX + p];
    float dx_ = lc[(a * 4 + 1) * NPIX + p];
    float dh  = lc[(a * 4 + 2) * NPIX + p];
    float dw  = lc[(a * 4 + 3) * NPIX + p];
    size_t lo = OFF_LOCS + (size_t)b * 350000 + (size_t)pa * 4;
    out[lo + 0] = dy; out[lo + 1] = dx_; out[lo + 2] = dh; out[lo + 3] = dw;

    float4 an = g_anchors[pa];
    float ah = an.z - an.x, aw = an.w - an.y;
    float acy = an.x + 0.5f * ah, acx = an.y + 0.5f * aw;
    float cy = dy * ah + acy, cx = dx_ * aw + acx;
    float hh = expf(dh) * ah, ww = expf(dw) * aw;
    float y1 = cy - 0.5f * hh, x1b = cx - 0.5f * ww;
    float y2 = cy + 0.5f * hh, x2b = cx + 0.5f * ww;
    y1 = fminf(fmaxf(y1, 0.f), 800.f);
    x1b = fminf(fmaxf(x1b, 0.f), 800.f);
    y2 = fminf(fmaxf(y2, 0.f), 800.f);
    x2b = fminf(fmaxf(x2b, 0.f), 800.f);
    float hs = y2 - y1, ws = x2b - x1b;
    bool valid = (hs >= 16.f) && (ws >= 16.f);
    float s = valid ? fg : -__int_as_float(0x7f800000);

    u32 sb = __float_as_uint(s);
    u32 mm = (sb & 0x80000000u) ? ~sb : (sb | 0x80000000u);
    u64 key = ((u64)(~mm) << 32) | (u32)pa;   // ascending key = best first
    g_keys[idx] = key;
    g_boxes[idx] = make_float4(y1, x1b, y2, x2b);
}

// ---------------- zero counters + valid bits ----------------
__global__ void zero_kernel()
{
    int t = threadIdx.x;
    if (t < 2) g_cnt[t] = 0;
    for (int i = t; i < 2 * NW; i += 256) g_validb[i] = 0ull;
}

// ---------------- zero both histograms ----------------
__global__ void zero_hist_kernel()
{
    int idx = blockIdx.x * blockDim.x + threadIdx.x;
    if (idx < 2 * 65536) { g_hist1[idx] = 0; g_hist2[idx] = 0; }
}

// ---------------- histogram pass (16-bit digits, warp-aggregated atomics) ----------------
__global__ void hist_kernel(int pass)
{
    int idx = blockIdx.x * blockDim.x + threadIdx.x;
    int lane = threadIdx.x & 31;
    bool ok = (idx < 2 * NANCH);
    int b = 0;
    u32 bin = 0;
    if (ok) {
        b = idx / NANCH;
        u64 k = g_keys[idx];
        if (pass == 0) {
            bin = (u32)(k >> 48);
        } else {
            if ((u32)(k >> 48) == g_prefix[b]) bin = (u32)((k >> 32) & 0xffffu);
            else ok = false;
        }
    }
    unsigned act = __ballot_sync(0xffffffffu, ok);
    if (ok) {
        u32 tag = (u32)b << 16 | bin;
        unsigned grp = __match_any_sync(act, tag);
        int leader = __ffs(grp) - 1;
        if (lane == leader) {
            u32* h = pass == 0 ? g_hist1 : g_hist2;
            atomicAdd(&h[b * 65536 + bin], (u32)__popc(grp));
        }
    }
}

// ---------------- scan 65536 bins, locate rank ----------------
__global__ void scan_kernel(int pass)
{
    int b = blockIdx.x;
    int tid = threadIdx.x;  // 1024
    const u32* base = (pass == 0 ? g_hist1 : g_hist2) + b * 65536;
    __shared__ u32 ssum[1024];
    u32 local = 0;
#pragma unroll 8
    for (int j = 0; j < 64; j++) local += base[tid * 64 + j];
    ssum[tid] = local;
    __syncthreads();
    // Hillis-Steele inclusive scan
    for (int off = 1; off < 1024; off <<= 1) {
        u32 v = (tid >= off) ? ssum[tid - off] : 0;
        __syncthreads();
        ssum[tid] += v;
        __syncthreads();
    }
    u32 incl = ssum[tid];
    u32 excl = incl - local;
    u32 rank = (pass == 0) ? (PRE_NMS - 1) : g_rank[b];
    if (excl <= rank && rank < incl) {
        u32 run = excl;
        for (int j = 0; j < 64; j++) {
            u32 c = base[tid * 64 + j];
            if (run + c > rank) {
                u32 digit = (u32)(tid * 64 + j);
                g_rank[b] = rank - run;
                if (pass == 0) g_prefix[b] = digit;
                else g_thresh[b] = (g_prefix[b] << 16) | digit;
                break;
            }
            run += c;
        }
    }
}

// ---------------- compact keys with score32 <= thresh ----------------
__global__ void compact_kernel()
{
    int idx = blockIdx.x * blockDim.x + threadIdx.x;
    if (idx >= 2 * NANCH) return;
    int b = idx / NANCH;
    u64 k = g_keys[idx];
    if ((u32)(k >> 32) <= g_thresh[b]) {
        int pos = atomicAdd(&g_cnt[b], 1);
        if (pos < TOPCAP) g_top[(size_t)b * TOPCAP + pos] = k;
    }
}

// ---------------- bitonic sort 8192 per batch ----------------
__global__ void sort_kernel()
{
    extern __shared__ u64 s[];
    int b = blockIdx.x;
    int tid = threadIdx.x;
    int cnt = g_cnt[b];
    if (cnt > TOPCAP) cnt = TOPCAP;
    for (int i = tid; i < TOPCAP; i += 1024)
        s[i] = (i < cnt) ? g_top[(size_t)b * TOPCAP + i] : ~0ull;
    __syncthreads();
    for (int k = 2; k <= TOPCAP; k <<= 1) {
        for (int j = k >> 1; j > 0; j >>= 1) {
            for (int t = tid; t < TOPCAP; t += 1024) {
                int ixj = t ^ j;
                if (ixj > t) {
                    bool up = ((t & k) == 0);
                    u64 x = s[t], y = s[ixj];
                    if ((x > y) == up) { s[t] = y; s[ixj] = x; }
                }
            }
            __syncthreads();
        }
    }
    for (int i = tid; i < PRE_NMS; i += 1024)
        g_top[(size_t)b * TOPCAP + i] = s[i];
}

// ---------------- gather sorted boxes + valid bits ----------------
__global__ void gather_kernel()
{
    int idx = blockIdx.x * blockDim.x + threadIdx.x;
    if (idx >= 2 * PRE_NMS) return;
    int b = idx / PRE_NMS;
    int j = idx - b * PRE_NMS;
    u64 k = g_top[(size_t)b * TOPCAP + j];
    u32 ai = (u32)(k & 0xffffffffull);
    g_nmsbox[idx] = g_boxes[(size_t)b * NANCH + ai];
    bool valid = ((u32)(k >> 32)) != 0xFF800000u;
    if (valid) atomicOr(&g_validb[b * NW + (j >> 6)], 1ull << (j & 63));
}

// ---------------- NMS IoU bitmask ----------------
__global__ void nms_mask_kernel()
{
    int cb = blockIdx.x, rb = blockIdx.y, b = blockIdx.z;
    int tid = threadIdx.x;
    __shared__ float4 cbox[64];
    int j = cb * 64 + tid;
    cbox[tid] = (j < PRE_NMS) ? g_nmsbox[(size_t)b * PRE_NMS + j]
                              : make_float4(0.f, 0.f, 0.f, 0.f);
    __syncthreads();
    int i = rb * 64 + tid;
    if (i >= PRE_NMS) return;
    float4 rr = g_nmsbox[(size_t)b * PRE_NMS + i];
    float areai = (rr.z - rr.x) * (rr.w - rr.y);
    u64 bits = 0ull;
#pragma unroll 4
    for (int c = 0; c < 64; c++) {
        int jj = cb * 64 + c;
        if (jj <= i || jj >= PRE_NMS) continue;
        float4 cc = cbox[c];
        float ty = fmaxf(rr.x, cc.x), tx = fmaxf(rr.y, cc.y);
        float by = fminf(rr.z, cc.z), bx2 = fminf(rr.w, cc.w);
        float wy = fmaxf(by - ty, 0.f), wx = fmaxf(bx2 - tx, 0.f);
        float inter = wy * wx;
        float areaj = (cc.z - cc.x) * (cc.w - cc.y);
        float iou = inter / (areai + areaj - inter + 1e-9f);
        if (iou > 0.7f) bits |= 1ull << c;
    }
    g_mask[((size_t)b * PRE_NMS + i) * NW + cb] = bits;
}

// ---------------- NMS sequential reduction v2: smem-chunked, cp.async double-buffered ----------------
__device__ __forceinline__ u32 smem_addr_of(const void* p)
{
    return (u32)__cvta_generic_to_shared(p);
}

__global__ void __launch_bounds__(256)
nms_reduce2_kernel()
{
    int b = blockIdx.x;
    int tid = threadIdx.x;
    extern __shared__ u64 sbuf[];   // [2][64][NW]
    __shared__ u64 remv[NW];
    __shared__ u64 svalid[NW];
    __shared__ u64 skeep;
    for (int v = tid; v < NW; v += 256) {
        remv[v] = 0ull;
        svalid[v] = g_validb[b * NW + v];
    }
    __syncthreads();

    // issue async copy of chunk w into buffer buf (all threads participate; one group each)
    auto issue_chunk = [&](int w, int buf) {
        int rows = PRE_NMS - w * 64;
        if (rows > 64) rows = 64;
        int total = rows * 47;                        // 47 x 16B per row (94 u64)
        const u64* gbase = g_mask + ((size_t)b * PRE_NMS + (size_t)w * 64) * NW;
        u64* sb0 = sbuf + (size_t)buf * 64 * NW;
        for (int e = tid; e < total; e += 256) {
            int r = e / 47, sg = e - r * 47;
            const u64* gp = gbase + (size_t)r * NW + sg * 2;
            u32 sa = smem_addr_of(sb0 + r * NW + sg * 2);
            asm volatile("cp.async.cg.shared.global [%0], [%1], 16;\n" :: "r"(sa), "l"(gp));
        }
        asm volatile("cp.async.commit_group;\n" ::);
    };

    issue_chunk(0, 0);
    for (int w = 0; w < NW; w++) {
        int buf = w & 1;
        if (w + 1 < NW) {
            issue_chunk(w + 1, buf ^ 1);
            asm volatile("cp.async.wait_group 1;\n" ::);
        } else {
            asm volatile("cp.async.wait_group 0;\n" ::);
        }
        __syncthreads();
        const u64* rowb = sbuf + (size_t)buf * 64 * NW;
        if (tid == 0) {
            u64 cur = svalid[w] & ~remv[w];
            u64 kp = 0ull;
            while (cur) {
                int bit = __ffsll((long long)cur) - 1;
                kp |= (1ull << bit);
                cur &= ~rowb[bit * NW + w];
                cur &= ~(1ull << bit);
            }
            skeep = kp;
            g_keepw[b * NW + w] = kp;
        }
        __syncthreads();
        u64 kp = skeep;
        for (int v = w + 1 + tid; v < NW; v += 256) {
            u64 acc = remv[v];
            u64 t = kp;
            while (t) {
                int bit = __ffsll((long long)t) - 1;
                t &= t - 1;
                acc |= rowb[bit * NW + v];
            }
            remv[v] = acc;
        }
        __syncthreads();
    }
}

// ---------------- finalize rois / roi_indices / roi_valid ----------------
__global__ void finalize_kernel(float* __restrict__ out)
{
    int b = blockIdx.x;
    int tid = threadIdx.x;   // 128 threads
    __shared__ u64 kw[NW];
    __shared__ u32 kscan[NW];
    __shared__ u32 ktot;
    __shared__ int sel[POST_NMS];
    for (int w = tid; w < NW; w += 128) kw[w] = g_keepw[b * NW + w];
    __syncthreads();
    if (tid == 0) {
        u32 r = 0;
        for (int w = 0; w < NW; w++) { kscan[w] = r; r += (u32)__popcll(kw[w]); }
        ktot = r;
    }
    __syncthreads();
    u32 ktot_l = ktot;
    for (int w = tid; w < NW; w += 128) {
        u64 bits = kw[w];
        u32 base = kscan[w];
        u64 t = bits;
        while (t) {
            int bit = __ffsll((long long)t) - 1;
            t &= t - 1;
            if (base < POST_NMS) sel[base] = w * 64 + bit;
            base++;
        }
        u64 lim = (w == NW - 1) ? ((1ull << 48) - 1ull) : ~0ull;  // 6000 = 93*64+48
        u64 nt = (~bits) & lim;
        while (nt) {
            int bit = __ffsll((long long)nt) - 1;
            nt &= nt - 1;
            int i = w * 64 + bit;
            u64 below = (bit == 0) ? 0ull : ((1ull << bit) - 1ull);
            u32 kept_before = kscan[w] + (u32)__popcll(bits & below);
            u32 slot = ktot_l + (u32)i - kept_before;
            if (slot < POST_NMS) sel[slot] = i;
        }
    }
    __syncthreads();
    for (int s2 = tid; s2 < POST_NMS; s2 += 128) {
        int i = sel[s2];
        int v = (int)((kw[i >> 6] >> (i & 63)) & 1ull);
        float4 bx = v ? g_nmsbox[(size_t)b * PRE_NMS + i] : make_float4(0.f, 0.f, 0.f, 0.f);
        size_t ro = OFF_ROIS + (size_t)b * POST_NMS * 4 + (size_t)s2 * 4;
        out[ro + 0] = bx.x; out[ro + 1] = bx.y; out[ro + 2] = bx.z; out[ro + 3] = bx.w;
        out[OFF_RIDX + (size_t)b * POST_NMS + s2] = (float)b;
        out[OFF_RVALID + (size_t)b * POST_NMS + s2] = (float)v;
    }
}

// ---------------- launch ----------------
extern "C" void kernel_launch(void* const* d_in, const int* in_sizes, int n_in,
                              void* d_out, int out_size)
{
    const float* feat   = (const float*)d_in[0];
    const float* convw  = (const float*)d_in[1];
    const float* convb  = (const float*)d_in[2];
    const float* scorew = (const float*)d_in[3];
    const float* scoreb = (const float*)d_in[4];
    const float* locw   = (const float*)d_in[5];
    const float* locb   = (const float*)d_in[6];
    float* out = (float*)d_out;

    cudaFuncSetAttribute(sort_kernel, cudaFuncAttributeMaxDynamicSharedMemorySize, 65536);
    cudaFuncSetAttribute(nms_reduce2_kernel, cudaFuncAttributeMaxDynamicSharedMemorySize, 2 * 64 * NW * 8);

    // launch order arranged so launch index 5 (ncu -s 5 -c 1) = conv3x3
    anchors_kernel<<<(NANCH + 127) / 128, 128>>>(out);                       // 0
    zero_kernel<<<1, 256>>>();                                               // 1
    zero_hist_kernel<<<(2 * 65536 + 255) / 256, 256>>>();                    // 2
    pad_kernel<<<(NCH * QPAD + 255) / 256, 256>>>(feat, 0);                  // 3
    pad_kernel<<<(NCH * QPAD + 255) / 256, 256>>>(feat, 1);                  // 4
    conv3x3_kernel<<<dim3(20, 4, 2), 256>>>(convw, convb);                   // 5  <- profiled
    gemm1x1_kernel<<<dim3(40, 2, 2), 256>>>(scorew, scoreb, 70, 0);          // 6
    gemm1x1_kernel<<<dim3(40, 3, 2), 256>>>(locw, locb, 140, 1);             // 7
    decode_kernel<<<(2 * NANCH + 255) / 256, 256>>>(out);                    // 8
    hist_kernel<<<(2 * NANCH + 255) / 256, 256>>>(0);                        // 9
    scan_kernel<<<2, 1024>>>(0);                                             // 10
    hist_kernel<<<(2 * NANCH + 255) / 256, 256>>>(1);                        // 11
    scan_kernel<<<2, 1024>>>(1);                                             // 12
    compact_kernel<<<(2 * NANCH + 255) / 256, 256>>>();                      // 13
    sort_kernel<<<2, 1024, 65536>>>();                                       // 14
    gather_kernel<<<(2 * PRE_NMS + 255) / 256, 256>>>();                     // 15
    nms_mask_kernel<<<dim3(NW, NW, 2), 64>>>();                              // 16
    nms_reduce2_kernel<<<2, 256, 2 * 64 * NW * 8>>>();                       // 17
    finalize_kernel<<<2, 128>>>(out);                                        // 18
}

// round 4
// speedup vs baseline: 1.5514x; 1.0167x over previous
#include <cuda_runtime.h>
#include <cuda_bf16.h>
#include <math.h>

typedef unsigned int u32;
typedef unsigned long long u64;

// ---------------- problem constants ----------------
#define NPIX    2500
#define HPAD    52
#define QPAD    2704          // 52*52
#define NCH     512
#define KTOT    4608          // 512*9
#define NA      35
#define NANCH   87500         // 2500*35
#define PRE_NMS 6000
#define POST_NMS 300
#define NW      94            // ceil(6000/64)
#define TOPCAP  8192

// output layout (float32, concatenated tuple)
#define OFF_LOCS    0
#define OFF_SCORES  700000
#define OFF_ROIS    1050000
#define OFF_RIDX    1052400
#define OFF_RVALID  1053000
#define OFF_ANCH    1053600

// packed dual-fp32 FMA: d = a*b + d (elementwise, IEEE rn, bit-exact vs 2x fmaf)
__device__ __forceinline__ void ffma2(u64& d, u64 a, u64 b)
{
    asm("fma.rn.f32x2 %0, %1, %2, %0;" : "+l"(d) : "l"(a), "l"(b));
}
__device__ __forceinline__ u64 pack2(float v)
{
    u64 r;
    u32 b = __float_as_uint(v);
    asm("mov.b64 %0, {%1, %1};" : "=l"(r) : "r"(b));
    return r;
}

// ---------------- device scratch (no allocation allowed) ----------------
__device__ __align__(16) float g_pad[2 * NCH * QPAD];
__device__ __align__(16) float g_h[2 * NCH * NPIX];
__device__ __align__(16) float g_scores[2 * 70 * NPIX];
__device__ __align__(16) float g_locs[2 * 140 * NPIX];
__device__ float4 g_anchors[NANCH];
__device__ u64    g_keys[2 * NANCH];
__device__ float4 g_boxes[2 * NANCH];
__device__ int    g_cnt[2];
__device__ u64    g_top[2 * TOPCAP];
__device__ float4 g_nmsbox[2 * PRE_NMS];
__device__ u64    g_mask[(size_t)2 * PRE_NMS * NW];
__device__ u64    g_validb[2 * NW];
__device__ u64    g_keepw[2 * NW];
__device__ u32    g_hist1[2 * 65536];
__device__ u32    g_hist2[2 * 65536];
__device__ u32    g_prefix[2];
__device__ u32    g_rank[2];
__device__ u32    g_thresh[2];

// ---------------- pad input (zero border) ----------------
__global__ void pad_kernel(const float* __restrict__ feat)
{
    int idx = blockIdx.x * blockDim.x + threadIdx.x;
    if (idx >= 2 * NCH * QPAD) return;
    int plane = idx / QPAD;
    int q = idx - plane * QPAD;
    int i = q / HPAD, j = q - i * HPAD;
    float v = 0.f;
    if (i >= 1 && i <= 50 && j >= 1 && j <= 50)
        v = feat[(size_t)plane * NPIX + (i - 1) * 50 + (j - 1)];
    g_pad[idx] = v;
}

// ---------------- anchors (fp64 base, fp32 add, clip) ----------------
__global__ void anchors_kernel(float* __restrict__ out)
{
    int idx = blockIdx.x * blockDim.x + threadIdx.x;
    if (idx >= NANCH) return;
    int p = idx / NA, a = idx - p * NA;
    int ri = a / 5, si = a - ri * 5;
    const double RAT[7] = {0.5, 0.66, 0.75, 1.0, 1.33, 1.5, 2.0};
    const double SCL[5] = {2.0, 4.0, 8.0, 16.0, 32.0};
    double hh = 16.0 * SCL[si] * sqrt(RAT[ri]);
    double ww = 16.0 * SCL[si] * sqrt(1.0 / RAT[ri]);
    float a0 = (float)(8.0 - hh / 2.0);
    float a1 = (float)(8.0 - ww / 2.0);
    float a2 = (float)(8.0 + hh / 2.0);
    float a3 = (float)(8.0 + ww / 2.0);
    int iy = p / 50, jx = p - iy * 50;
    float sy = (float)(iy * 16), sx = (float)(jx * 16);
    float y1 = fminf(fmaxf(a0 + sy, 0.f), 799.f);
    float x1 = fminf(fmaxf(a1 + sx, 0.f), 799.f);
    float y2 = fminf(fmaxf(a2 + sy, 0.f), 799.f);
    float x2 = fminf(fmaxf(a3 + sx, 0.f), 799.f);
    g_anchors[idx] = make_float4(y1, x1, y2, x2);
    size_t o = OFF_ANCH + (size_t)idx * 4;
    out[o + 0] = y1; out[o + 1] = x1; out[o + 2] = y2; out[o + 3] = x2;
}

// ---------------- conv3x3 + bias + relu as implicit GEMM (FFMA2 mainloop) ----------------
__global__ void __launch_bounds__(256, 2)
conv3x3_kernel(const float* __restrict__ W, const float* __restrict__ bias)
{
    const int bx = blockIdx.x;     // pixel tile (20)
    const int by = blockIdx.y;     // co tile (4)
    const int bz = blockIdx.z;     // batch
    const int tid = threadIdx.x;
    const int n0 = bx * 128;
    const int m0 = by * 128;
    __shared__ __align__(16) float As[8][128];
    __shared__ __align__(16) float Bs[8][128];
    const int tm = tid >> 4;
    const int tn = tid & 15;
    u64 acc2[8][4];                // 8 co x 4 pixel-pairs (=8 pixels)
#pragma unroll
    for (int u = 0; u < 8; u++)
#pragma unroll
        for (int v = 0; v < 4; v++) acc2[u][v] = 0ull;

    const int a_co = tid >> 1;
    const int a_kq = (tid & 1) * 4;
    const int b_kk = tid >> 5;
    const int b_pl = (tid & 31) * 4;
    const float* padB = g_pad + (size_t)bz * NCH * QPAD;

    for (int k0 = 0; k0 < KTOT; k0 += 8) {
        float4 av4 = *(const float4*)&W[(size_t)(m0 + a_co) * KTOT + k0 + a_kq];
        int k = k0 + b_kk;
        int ci = k / 9;
        int r = k - ci * 9;
        int dy = r / 3, dx = r - dy * 3;
        const float* pp = padB + (size_t)ci * QPAD;
        float bv[4];
#pragma unroll
        for (int q = 0; q < 4; q++) {
            int p = n0 + b_pl + q;
            if (p < NPIX) {
                int i = p / 50, j = p - 50 * i;
                bv[q] = pp[(i + dy) * HPAD + (j + dx)];
            } else bv[q] = 0.f;
        }
        __syncthreads();
        As[a_kq + 0][a_co] = av4.x;
        As[a_kq + 1][a_co] = av4.y;
        As[a_kq + 2][a_co] = av4.z;
        As[a_kq + 3][a_co] = av4.w;
        Bs[b_kk][b_pl + 0] = bv[0];
        Bs[b_kk][b_pl + 1] = bv[1];
        Bs[b_kk][b_pl + 2] = bv[2];
        Bs[b_kk][b_pl + 3] = bv[3];
        __syncthreads();
#pragma unroll
        for (int kk = 0; kk < 8; kk++) {
            float4 aa0 = *(const float4*)&As[kk][tm * 8];
            float4 aa1 = *(const float4*)&As[kk][tm * 8 + 4];
            ulonglong2 bq0 = *(const ulonglong2*)&Bs[kk][tn * 8];
            ulonglong2 bq1 = *(const ulonglong2*)&Bs[kk][tn * 8 + 4];
            u64 bp[4] = {bq0.x, bq0.y, bq1.x, bq1.y};
            u64 ap[8];
            ap[0] = pack2(aa0.x); ap[1] = pack2(aa0.y);
            ap[2] = pack2(aa0.z); ap[3] = pack2(aa0.w);
            ap[4] = pack2(aa1.x); ap[5] = pack2(aa1.y);
            ap[6] = pack2(aa1.z); ap[7] = pack2(aa1.w);
#pragma unroll
            for (int u = 0; u < 8; u++)
#pragma unroll
                for (int v = 0; v < 4; v++)
                    ffma2(acc2[u][v], ap[u], bp[v]);
        }
    }
#pragma unroll
    for (int u = 0; u < 8; u++) {
        int co = m0 + tm * 8 + u;
        float bb = bias[co];
        float* outrow = g_h + ((size_t)bz * NCH + co) * NPIX;
#pragma unroll
        for (int v = 0; v < 4; v++) {
            u32 lo = (u32)(acc2[u][v] & 0xffffffffull);
            u32 hi = (u32)(acc2[u][v] >> 32);
            int p = n0 + tn * 8 + v * 2;
            if (p < NPIX)     outrow[p]     = fmaxf(__uint_as_float(lo) + bb, 0.f);
            if (p + 1 < NPIX) outrow[p + 1] = fmaxf(__uint_as_float(hi) + bb, 0.f);
        }
    }
}

// ---------------- 1x1 conv GEMM (FFMA2) ----------------
__global__ void __launch_bounds__(256)
gemm1x1_kernel(const float* __restrict__ W, const float* __restrict__ bias, int M, int mode)
{
    const int bx = blockIdx.x;
    const int by = blockIdx.y;
    const int bz = blockIdx.z;
    const int tid = threadIdx.x;
    const int n0 = bx * 64;
    const int m0 = by * 64;
    __shared__ __align__(16) float As[16][64];
    __shared__ __align__(16) float Bs[16][64];
    const int tm = tid >> 4, tn = tid & 15;
    u64 acc2[4][2];
#pragma unroll
    for (int u = 0; u < 4; u++)
#pragma unroll
        for (int v = 0; v < 2; v++) acc2[u][v] = 0ull;

    const int a_co = tid >> 2;
    const int a_kq = (tid & 3) * 4;
    const int b_kk = tid >> 4;
    const int b_p0 = (tid & 15) * 4;
    const float* Hb = g_h + (size_t)bz * NCH * NPIX;

    for (int k0 = 0; k0 < NCH; k0 += 16) {
        int co = m0 + a_co;
        float4 av = make_float4(0.f, 0.f, 0.f, 0.f);
        if (co < M) av = *(const float4*)&W[(size_t)co * NCH + k0 + a_kq];
        int p0 = n0 + b_p0;
        float4 bv = make_float4(0.f, 0.f, 0.f, 0.f);
        if (p0 < NPIX) bv = *(const float4*)&Hb[(size_t)(k0 + b_kk) * NPIX + p0];
        __syncthreads();
        As[a_kq + 0][a_co] = av.x;
        As[a_kq + 1][a_co] = av.y;
        As[a_kq + 2][a_co] = av.z;
        As[a_kq + 3][a_co] = av.w;
        *(float4*)&Bs[b_kk][b_p0] = bv;
        __syncthreads();
#pragma unroll
        for (int kk = 0; kk < 16; kk++) {
            float4 aa = *(const float4*)&As[kk][tm * 4];
            ulonglong2 bq = *(const ulonglong2*)&Bs[kk][tn * 4];
            u64 bp[2] = {bq.x, bq.y};
            u64 ap[4] = {pack2(aa.x), pack2(aa.y), pack2(aa.z), pack2(aa.w)};
#pragma unroll
            for (int u = 0; u < 4; u++)
#pragma unroll
                for (int v = 0; v < 2; v++)
                    ffma2(acc2[u][v], ap[u], bp[v]);
        }
    }
    float* outbase = mode ? g_locs : g_scores;
#pragma unroll
    for (int u = 0; u < 4; u++) {
        int co = m0 + tm * 4 + u;
        if (co >= M) continue;
        float bb = bias[co];
        float* orow = outbase + ((size_t)bz * M + co) * NPIX;
#pragma unroll
        for (int v = 0; v < 2; v++) {
            u32 lo = (u32)(acc2[u][v] & 0xffffffffull);
            u32 hi = (u32)(acc2[u][v] >> 32);
            int p = n0 + tn * 4 + v * 2;
            if (p < NPIX)     orow[p]     = __uint_as_float(lo) + bb;
            if (p + 1 < NPIX) orow[p + 1] = __uint_as_float(hi) + bb;
        }
    }
}

// ---------------- decode boxes, softmax fg, keys ----------------
__global__ void decode_kernel(float* __restrict__ out)
{
    int idx = blockIdx.x * blockDim.x + threadIdx.x;
    if (idx >= 2 * NANCH) return;
    int b = idx / NANCH;
    int pa = idx - b * NANCH;
    int p = pa / NA;
    int a = pa - p * NA;

    const float* sc = g_scores + (size_t)b * 70 * NPIX;
    float x0 = sc[(a * 2 + 0) * NPIX + p];
    float x1 = sc[(a * 2 + 1) * NPIX + p];
    size_t so = OFF_SCORES + (size_t)b * 175000 + (size_t)pa * 2;
    out[so + 0] = x0;
    out[so + 1] = x1;
    float mx = fmaxf(x0, x1);
    float e0 = expf(x0 - mx), e1 = expf(x1 - mx);
    float fg = e1 / (e0 + e1);

    const float* lc = g_locs + (size_t)b * 140 * NPIX;
    float dy  = lc[(a * 4 + 0) * NPIX + p];
    float dx_ = lc[(a * 4 + 1) * NPIX + p];
    float dh  = lc[(a * 4 + 2) * NPIX + p];
    float dw  = lc[(a * 4 + 3) * NPIX + p];
    size_t lo = OFF_LOCS + (size_t)b * 350000 + (size_t)pa * 4;
    out[lo + 0] = dy; out[lo + 1] = dx_; out[lo + 2] = dh; out[lo + 3] = dw;

    float4 an = g_anchors[pa];
    float ah = an.z - an.x, aw = an.w - an.y;
    float acy = an.x + 0.5f * ah, acx = an.y + 0.5f * aw;
    float cy = dy * ah + acy, cx = dx_ * aw + acx;
    float hh = expf(dh) * ah, ww = expf(dw) * aw;
    float y1 = cy - 0.5f * hh, x1b = cx - 0.5f * ww;
    float y2 = cy + 0.5f * hh, x2b = cx + 0.5f * ww;
    y1 = fminf(fmaxf(y1, 0.f), 800.f);
    x1b = fminf(fmaxf(x1b, 0.f), 800.f);
    y2 = fminf(fmaxf(y2, 0.f), 800.f);
    x2b = fminf(fmaxf(x2b, 0.f), 800.f);
    float hs = y2 - y1, ws = x2b - x1b;
    bool valid = (hs >= 16.f) && (ws >= 16.f);
    float s = valid ? fg : -__int_as_float(0x7f800000);

    u32 sb = __float_as_uint(s);
    u32 mm = (sb & 0x80000000u) ? ~sb : (sb | 0x80000000u);
    u64 key = ((u64)(~mm) << 32) | (u32)pa;   // ascending key = best first
    g_keys[idx] = key;
    g_boxes[idx] = make_float4(y1, x1b, y2, x2b);
}

// ---------------- zero counters + valid bits ----------------
__global__ void zero_kernel()
{
    int t = threadIdx.x;
    if (t < 2) g_cnt[t] = 0;
    for (int i = t; i < 2 * NW; i += 256) g_validb[i] = 0ull;
}

// ---------------- zero both histograms ----------------
__global__ void zero_hist_kernel()
{
    int idx = blockIdx.x * blockDim.x + threadIdx.x;
    if (idx < 2 * 65536) { g_hist1[idx] = 0; g_hist2[idx] = 0; }
}

// ---------------- histogram pass (16-bit digits, warp-aggregated atomics) ----------------
__global__ void hist_kernel(int pass)
{
    int idx = blockIdx.x * blockDim.x + threadIdx.x;
    int lane = threadIdx.x & 31;
    bool ok = (idx < 2 * NANCH);
    int b = 0;
    u32 bin = 0;
    if (ok) {
        b = idx / NANCH;
        u64 k = g_keys[idx];
        if (pass == 0) {
            bin = (u32)(k >> 48);
        } else {
            if ((u32)(k >> 48) == g_prefix[b]) bin = (u32)((k >> 32) & 0xffffu);
            else ok = false;
        }
    }
    unsigned act = __ballot_sync(0xffffffffu, ok);
    if (ok) {
        u32 tag = (u32)b << 16 | bin;
        unsigned grp = __match_any_sync(act, tag);
        int leader = __ffs(grp) - 1;
        if (lane == leader) {
            u32* h = pass == 0 ? g_hist1 : g_hist2;
            atomicAdd(&h[b * 65536 + bin], (u32)__popc(grp));
        }
    }
}

// ---------------- scan 65536 bins, locate rank ----------------
__global__ void scan_kernel(int pass)
{
    int b = blockIdx.x;
    int tid = threadIdx.x;  // 1024
    const u32* base = (pass == 0 ? g_hist1 : g_hist2) + b * 65536;
    __shared__ u32 ssum[1024];
    u32 local = 0;
#pragma unroll 8
    for (int j = 0; j < 64; j++) local += base[tid * 64 + j];
    ssum[tid] = local;
    __syncthreads();
    for (int off = 1; off < 1024; off <<= 1) {
        u32 v = (tid >= off) ? ssum[tid - off] : 0;
        __syncthreads();
        ssum[tid] += v;
        __syncthreads();
    }
    u32 incl = ssum[tid];
    u32 excl = incl - local;
    u32 rank = (pass == 0) ? (PRE_NMS - 1) : g_rank[b];
    if (excl <= rank && rank < incl) {
        u32 run = excl;
        for (int j = 0; j < 64; j++) {
            u32 c = base[tid * 64 + j];
            if (run + c > rank) {
                u32 digit = (u32)(tid * 64 + j);
                g_rank[b] = rank - run;
                if (pass == 0) g_prefix[b] = digit;
                else g_thresh[b] = (g_prefix[b] << 16) | digit;
                break;
            }
            run += c;
        }
    }
}

// ---------------- compact keys with score32 <= thresh ----------------
__global__ void compact_kernel()
{
    int idx = blockIdx.x * blockDim.x + threadIdx.x;
    if (idx >= 2 * NANCH) return;
    int b = idx / NANCH;
    u64 k = g_keys[idx];
    if ((u32)(k >> 32) <= g_thresh[b]) {
        int pos = atomicAdd(&g_cnt[b], 1);
        if (pos < TOPCAP) g_top[(size_t)b * TOPCAP + pos] = k;
    }
}

// ---------------- bitonic sort 8192 per batch ----------------
__global__ void sort_kernel()
{
    extern __shared__ u64 s[];
    int b = blockIdx.x;
    int tid = threadIdx.x;
    int cnt = g_cnt[b];
    if (cnt > TOPCAP) cnt = TOPCAP;
    for (int i = tid; i < TOPCAP; i += 1024)
        s[i] = (i < cnt) ? g_top[(size_t)b * TOPCAP + i] : ~0ull;
    __syncthreads();
    for (int k = 2; k <= TOPCAP; k <<= 1) {
        for (int j = k >> 1; j > 0; j >>= 1) {
            for (int t = tid; t < TOPCAP; t += 1024) {
                int ixj = t ^ j;
                if (ixj > t) {
                    bool up = ((t & k) == 0);
                    u64 x = s[t], y = s[ixj];
                    if ((x > y) == up) { s[t] = y; s[ixj] = x; }
                }
            }
            __syncthreads();
        }
    }
    for (int i = tid; i < PRE_NMS; i += 1024)
        g_top[(size_t)b * TOPCAP + i] = s[i];
}

// ---------------- gather sorted boxes + valid bits ----------------
__global__ void gather_kernel()
{
    int idx = blockIdx.x * blockDim.x + threadIdx.x;
    if (idx >= 2 * PRE_NMS) return;
    int b = idx / PRE_NMS;
    int j = idx - b * PRE_NMS;
    u64 k = g_top[(size_t)b * TOPCAP + j];
    u32 ai = (u32)(k & 0xffffffffull);
    g_nmsbox[idx] = g_boxes[(size_t)b * NANCH + ai];
    bool valid = ((u32)(k >> 32)) != 0xFF800000u;
    if (valid) atomicOr(&g_validb[b * NW + (j >> 6)], 1ull << (j & 63));
}

// ---------------- NMS IoU bitmask ----------------
__global__ void nms_mask_kernel()
{
    int cb = blockIdx.x, rb = blockIdx.y, b = blockIdx.z;
    int tid = threadIdx.x;
    __shared__ float4 cbox[64];
    int j = cb * 64 + tid;
    cbox[tid] = (j < PRE_NMS) ? g_nmsbox[(size_t)b * PRE_NMS + j]
                              : make_float4(0.f, 0.f, 0.f, 0.f);
    __syncthreads();
    int i = rb * 64 + tid;
    if (i >= PRE_NMS) return;
    float4 rr = g_nmsbox[(size_t)b * PRE_NMS + i];
    float areai = (rr.z - rr.x) * (rr.w - rr.y);
    u64 bits = 0ull;
#pragma unroll 4
    for (int c = 0; c < 64; c++) {
        int jj = cb * 64 + c;
        if (jj <= i || jj >= PRE_NMS) continue;
        float4 cc = cbox[c];
        float ty = fmaxf(rr.x, cc.x), tx = fmaxf(rr.y, cc.y);
        float by = fminf(rr.z, cc.z), bx2 = fminf(rr.w, cc.w);
        float wy = fmaxf(by - ty, 0.f), wx = fmaxf(bx2 - tx, 0.f);
        float inter = wy * wx;
        float areaj = (cc.z - cc.x) * (cc.w - cc.y);
        float iou = inter / (areai + areaj - inter + 1e-9f);
        if (iou > 0.7f) bits |= 1ull << c;
    }
    g_mask[((size_t)b * PRE_NMS + i) * NW + cb] = bits;
}

// ---------------- NMS sequential reduction: smem-chunked, cp.async double-buffered ----------------
__device__ __forceinline__ u32 smem_addr_of(const void* p)
{
    return (u32)__cvta_generic_to_shared(p);
}

__global__ void __launch_bounds__(256)
nms_reduce2_kernel()
{
    int b = blockIdx.x;
    int tid = threadIdx.x;
    extern __shared__ u64 sbuf[];   // [2][64][NW]
    __shared__ u64 remv[NW];
    __shared__ u64 svalid[NW];
    __shared__ u64 skeep;
    for (int v = tid; v < NW; v += 256) {
        remv[v] = 0ull;
        svalid[v] = g_validb[b * NW + v];
    }
    __syncthreads();

    auto issue_chunk = [&](int w, int buf) {
        int rows = PRE_NMS - w * 64;
        if (rows > 64) rows = 64;
        int total = rows * 47;
        const u64* gbase = g_mask + ((size_t)b * PRE_NMS + (size_t)w * 64) * NW;
        u64* sb0 = sbuf + (size_t)buf * 64 * NW;
        for (int e = tid; e < total; e += 256) {
            int r = e / 47, sg = e - r * 47;
            const u64* gp = gbase + (size_t)r * NW + sg * 2;
            u32 sa = smem_addr_of(sb0 + r * NW + sg * 2);
            asm volatile("cp.async.cg.shared.global [%0], [%1], 16;\n" :: "r"(sa), "l"(gp));
        }
        asm volatile("cp.async.commit_group;\n" ::);
    };

    issue_chunk(0, 0);
    for (int w = 0; w < NW; w++) {
        int buf = w & 1;
        if (w + 1 < NW) {
            issue_chunk(w + 1, buf ^ 1);
            asm volatile("cp.async.wait_group 1;\n" ::);
        } else {
            asm volatile("cp.async.wait_group 0;\n" ::);
        }
        __syncthreads();
        const u64* rowb = sbuf + (size_t)buf * 64 * NW;
        if (tid == 0) {
            u64 cur = svalid[w] & ~remv[w];
            u64 kp = 0ull;
            while (cur) {
                int bit = __ffsll((long long)cur) - 1;
                kp |= (1ull << bit);
                cur &= ~rowb[bit * NW + w];
                cur &= ~(1ull << bit);
            }
            skeep = kp;
            g_keepw[b * NW + w] = kp;
        }
        __syncthreads();
        u64 kp = skeep;
        for (int v = w + 1 + tid; v < NW; v += 256) {
            u64 acc = remv[v];
            u64 t = kp;
            while (t) {
                int bit = __ffsll((long long)t) - 1;
                t &= t - 1;
                acc |= rowb[bit * NW + v];
            }
            remv[v] = acc;
        }
        __syncthreads();
    }
}

// ---------------- finalize rois / roi_indices / roi_valid ----------------
__global__ void finalize_kernel(float* __restrict__ out)
{
    int b = blockIdx.x;
    int tid = threadIdx.x;   // 128 threads
    __shared__ u64 kw[NW];
    __shared__ u32 kscan[NW];
    __shared__ u32 ktot;
    __shared__ int sel[POST_NMS];
    for (int w = tid; w < NW; w += 128) kw[w] = g_keepw[b * NW + w];
    __syncthreads();
    if (tid == 0) {
        u32 r = 0;
        for (int w = 0; w < NW; w++) { kscan[w] = r; r += (u32)__popcll(kw[w]); }
        ktot = r;
    }
    __syncthreads();
    u32 ktot_l = ktot;
    for (int w = tid; w < NW; w += 128) {
        u64 bits = kw[w];
        u32 base = kscan[w];
        u64 t = bits;
        while (t) {
            int bit = __ffsll((long long)t) - 1;
            t &= t - 1;
            if (base < POST_NMS) sel[base] = w * 64 + bit;
            base++;
        }
        u64 lim = (w == NW - 1) ? ((1ull << 48) - 1ull) : ~0ull;  // 6000 = 93*64+48
        u64 nt = (~bits) & lim;
        while (nt) {
            int bit = __ffsll((long long)nt) - 1;
            nt &= nt - 1;
            int i = w * 64 + bit;
            u64 below = (bit == 0) ? 0ull : ((1ull << bit) - 1ull);
            u32 kept_before = kscan[w] + (u32)__popcll(bits & below);
            u32 slot = ktot_l + (u32)i - kept_before;
            if (slot < POST_NMS) sel[slot] = i;
        }
    }
    __syncthreads();
    for (int s2 = tid; s2 < POST_NMS; s2 += 128) {
        int i = sel[s2];
        int v = (int)((kw[i >> 6] >> (i & 63)) & 1ull);
        float4 bx = v ? g_nmsbox[(size_t)b * PRE_NMS + i] : make_float4(0.f, 0.f, 0.f, 0.f);
        size_t ro = OFF_ROIS + (size_t)b * POST_NMS * 4 + (size_t)s2 * 4;
        out[ro + 0] = bx.x; out[ro + 1] = bx.y; out[ro + 2] = bx.z; out[ro + 3] = bx.w;
        out[OFF_RIDX + (size_t)b * POST_NMS + s2] = (float)b;
        out[OFF_RVALID + (size_t)b * POST_NMS + s2] = (float)v;
    }
}

// ---------------- launch ----------------
extern "C" void kernel_launch(void* const* d_in, const int* in_sizes, int n_in,
                              void* d_out, int out_size)
{
    const float* feat   = (const float*)d_in[0];
    const float* convw  = (const float*)d_in[1];
    const float* convb  = (const float*)d_in[2];
    const float* scorew = (const float*)d_in[3];
    const float* scoreb = (const float*)d_in[4];
    const float* locw   = (const float*)d_in[5];
    const float* locb   = (const float*)d_in[6];
    float* out = (float*)d_out;

    cudaFuncSetAttribute(sort_kernel, cudaFuncAttributeMaxDynamicSharedMemorySize, 65536);
    cudaFuncSetAttribute(nms_reduce2_kernel, cudaFuncAttributeMaxDynamicSharedMemorySize, 2 * 64 * NW * 8);

    // order arranged so the ncu-captured slot (observed = our index 4) = conv3x3
    zero_kernel<<<1, 256>>>();                                               // 0
    zero_hist_kernel<<<(2 * 65536 + 255) / 256, 256>>>();                    // 1
    anchors_kernel<<<(NANCH + 127) / 128, 128>>>(out);                       // 2
    pad_kernel<<<(2 * NCH * QPAD + 255) / 256, 256>>>(feat);                 // 3
    conv3x3_kernel<<<dim3(20, 4, 2), 256>>>(convw, convb);                   // 4  <- profiled
    gemm1x1_kernel<<<dim3(40, 2, 2), 256>>>(scorew, scoreb, 70, 0);          // 5
    gemm1x1_kernel<<<dim3(40, 3, 2), 256>>>(locw, locb, 140, 1);             // 6
    decode_kernel<<<(2 * NANCH + 255) / 256, 256>>>(out);                    // 7
    hist_kernel<<<(2 * NANCH + 255) / 256, 256>>>(0);                        // 8
    scan_kernel<<<2, 1024>>>(0);                                             // 9
    hist_kernel<<<(2 * NANCH + 255) / 256, 256>>>(1);                        // 10
    scan_kernel<<<2, 1024>>>(1);                                             // 11
    compact_kernel<<<(2 * NANCH + 255) / 256, 256>>>();                      // 12
    sort_kernel<<<2, 1024, 65536>>>();                                       // 13
    gather_kernel<<<(2 * PRE_NMS + 255) / 256, 256>>>();                     // 14
    nms_mask_kernel<<<dim3(NW, NW, 2), 64>>>();                              // 15
    nms_reduce2_kernel<<<2, 256, 2 * 64 * NW * 8>>>();                       // 16
    finalize_kernel<<<2, 128>>>(out);                                        // 17
}

// round 6
// speedup vs baseline: 1.7622x; 1.1359x over previous
#include <cuda_runtime.h>
#include <cuda_bf16.h>
#include <math.h>

typedef unsigned int u32;
typedef unsigned long long u64;

// ---------------- problem constants ----------------
#define NPIX    2500
#define HPAD    52
#define QPAD    2704          // 52*52
#define NCH     512
#define KTOT    4608          // 512*9
#define NA      35
#define NANCH   87500         // 2500*35
#define PRE_NMS 6000
#define POST_NMS 300
#define NW      94            // ceil(6000/64)
#define TOPCAP  8192

// output layout (float32, concatenated tuple)
#define OFF_LOCS    0
#define OFF_SCORES  700000
#define OFF_ROIS    1050000
#define OFF_RIDX    1052400
#define OFF_RVALID  1053000
#define OFF_ANCH    1053600

// ---------------- device scratch (no allocation allowed) ----------------
__device__ __align__(16) float g_pad[2 * NCH * QPAD];
__device__ __align__(16) float g_h[2 * NCH * NPIX];
__device__ __align__(16) float g_scores[2 * 70 * NPIX];
__device__ __align__(16) float g_locs[2 * 140 * NPIX];
__device__ float4 g_anchors[NANCH];
__device__ u64    g_keys[2 * NANCH];
__device__ float4 g_boxes[2 * NANCH];
__device__ int    g_cnt[2];
__device__ u64    g_top[2 * TOPCAP];
__device__ float4 g_nmsbox[2 * PRE_NMS];
__device__ u64    g_mask[(size_t)2 * PRE_NMS * NW];
__device__ u64    g_validb[2 * NW];
__device__ u64    g_keepw[2 * NW];
__device__ u32    g_hist1[2 * 65536];
__device__ u32    g_hist2[2 * 65536];
__device__ u32    g_prefix[2];
__device__ u32    g_rank[2];
__device__ u32    g_thresh[2];

// ---------------- pad input (zero border) ----------------
__global__ void pad_kernel(const float* __restrict__ feat)
{
    int idx = blockIdx.x * blockDim.x + threadIdx.x;
    if (idx >= 2 * NCH * QPAD) return;
    int plane = idx / QPAD;
    int q = idx - plane * QPAD;
    int i = q / HPAD, j = q - i * HPAD;
    float v = 0.f;
    if (i >= 1 && i <= 50 && j >= 1 && j <= 50)
        v = feat[(size_t)plane * NPIX + (i - 1) * 50 + (j - 1)];
    g_pad[idx] = v;
}

// ---------------- anchors (fp64 base, fp32 add, clip) ----------------
__global__ void anchors_kernel(float* __restrict__ out)
{
    int idx = blockIdx.x * blockDim.x + threadIdx.x;
    if (idx >= NANCH) return;
    int p = idx / NA, a = idx - p * NA;
    int ri = a / 5, si = a - ri * 5;
    const double RAT[7] = {0.5, 0.66, 0.75, 1.0, 1.33, 1.5, 2.0};
    const double SCL[5] = {2.0, 4.0, 8.0, 16.0, 32.0};
    double hh = 16.0 * SCL[si] * sqrt(RAT[ri]);
    double ww = 16.0 * SCL[si] * sqrt(1.0 / RAT[ri]);
    float a0 = (float)(8.0 - hh / 2.0);
    float a1 = (float)(8.0 - ww / 2.0);
    float a2 = (float)(8.0 + hh / 2.0);
    float a3 = (float)(8.0 + ww / 2.0);
    int iy = p / 50, jx = p - iy * 50;
    float sy = (float)(iy * 16), sx = (float)(jx * 16);
    float y1 = fminf(fmaxf(a0 + sy, 0.f), 799.f);
    float x1 = fminf(fmaxf(a1 + sx, 0.f), 799.f);
    float y2 = fminf(fmaxf(a2 + sy, 0.f), 799.f);
    float x2 = fminf(fmaxf(a3 + sx, 0.f), 799.f);
    g_anchors[idx] = make_float4(y1, x1, y2, x2);
    size_t o = OFF_ANCH + (size_t)idx * 4;
    out[o + 0] = y1; out[o + 1] = x1; out[o + 2] = y2; out[o + 3] = x2;
}

// ---------------- conv3x3 + bias + relu as implicit GEMM ----------------
// tile 128co x 80pix, 256 threads, 8x5 micro-tile, KB=8
// grid = 32 pix-tiles x 4 co-tiles x 2 batch = 256 blocks <= 296 occ-2 slots (one wave)
#define PTILE 80
__global__ void __launch_bounds__(256, 2)
conv3x3_kernel(const float* __restrict__ W, const float* __restrict__ bias)
{
    const int bx = blockIdx.x;     // pixel tile (32)
    const int by = blockIdx.y;     // co tile (4)
    const int bz = blockIdx.z;     // batch
    const int tid = threadIdx.x;
    const int n0 = bx * PTILE;
    const int m0 = by * 128;
    __shared__ __align__(16) float As[8][128];
    __shared__ __align__(16) float Bs[8][PTILE];
    const int tm = tid >> 4;       // 0..15 -> 8 co each
    const int tn = tid & 15;       // 0..15 -> 5 pix each
    float acc[8][5];
#pragma unroll
    for (int u = 0; u < 8; u++)
#pragma unroll
        for (int v = 0; v < 5; v++) acc[u][v] = 0.f;

    const int a_co = tid >> 1;             // 0..127
    const int a_kq = (tid & 1) * 4;        // 0 / 4
    const int b_kk = tid >> 5;             // 0..7
    const int b_px = tid & 31;             // 0..31
    const float* padB = g_pad + (size_t)bz * NCH * QPAD;

    for (int k0 = 0; k0 < KTOT; k0 += 8) {
        float4 av4 = *(const float4*)&W[(size_t)(m0 + a_co) * KTOT + k0 + a_kq];
        int k = k0 + b_kk;
        int ci = k / 9;
        int r = k - ci * 9;
        int dy = r / 3, dx = r - dy * 3;
        const float* pp = padB + (size_t)ci * QPAD + (size_t)dy * HPAD + dx;
        float bv[3];
#pragma unroll
        for (int e = 0; e < 3; e++) {
            int px = b_px + e * 32;
            int p = n0 + px;
            bv[e] = 0.f;
            if (px < PTILE && p < NPIX) {
                int i = p / 50, j = p - 50 * i;
                bv[e] = pp[i * HPAD + j];
            }
        }
        __syncthreads();
        As[a_kq + 0][a_co] = av4.x;
        As[a_kq + 1][a_co] = av4.y;
        As[a_kq + 2][a_co] = av4.z;
        As[a_kq + 3][a_co] = av4.w;
#pragma unroll
        for (int e = 0; e < 3; e++) {
            int px = b_px + e * 32;
            if (px < PTILE) Bs[b_kk][px] = bv[e];
        }
        __syncthreads();
#pragma unroll
        for (int kk = 0; kk < 8; kk++) {
            float4 aa0 = *(const float4*)&As[kk][tm * 8];
            float4 aa1 = *(const float4*)&As[kk][tm * 8 + 4];
            float aarr[8] = {aa0.x, aa0.y, aa0.z, aa0.w, aa1.x, aa1.y, aa1.z, aa1.w};
            float barr[5];
#pragma unroll
            for (int v = 0; v < 5; v++) barr[v] = Bs[kk][tn * 5 + v];
#pragma unroll
            for (int u = 0; u < 8; u++)
#pragma unroll
                for (int v = 0; v < 5; v++)
                    acc[u][v] = fmaf(aarr[u], barr[v], acc[u][v]);
        }
    }
#pragma unroll
    for (int u = 0; u < 8; u++) {
        int co = m0 + tm * 8 + u;
        float bb = bias[co];
        float* outrow = g_h + ((size_t)bz * NCH + co) * NPIX;
#pragma unroll
        for (int v = 0; v < 5; v++) {
            int p = n0 + tn * 5 + v;
            if (p < NPIX) outrow[p] = fmaxf(acc[u][v] + bb, 0.f);
        }
    }
}

// ---------------- 1x1 conv GEMM ----------------
__global__ void __launch_bounds__(256)
gemm1x1_kernel(const float* __restrict__ W, const float* __restrict__ bias, int M, int mode)
{
    const int bx = blockIdx.x;
    const int by = blockIdx.y;
    const int bz = blockIdx.z;
    const int tid = threadIdx.x;
    const int n0 = bx * 64;
    const int m0 = by * 64;
    __shared__ __align__(16) float As[16][64];
    __shared__ __align__(16) float Bs[16][64];
    const int tm = tid >> 4, tn = tid & 15;
    float acc[4][4];
#pragma unroll
    for (int u = 0; u < 4; u++)
#pragma unroll
        for (int v = 0; v < 4; v++) acc[u][v] = 0.f;

    const int a_co = tid >> 2;
    const int a_kq = (tid & 3) * 4;
    const int b_kk = tid >> 4;
    const int b_p0 = (tid & 15) * 4;
    const float* Hb = g_h + (size_t)bz * NCH * NPIX;

    for (int k0 = 0; k0 < NCH; k0 += 16) {
        int co = m0 + a_co;
        float4 av = make_float4(0.f, 0.f, 0.f, 0.f);
        if (co < M) av = *(const float4*)&W[(size_t)co * NCH + k0 + a_kq];
        int p0 = n0 + b_p0;
        float4 bv = make_float4(0.f, 0.f, 0.f, 0.f);
        if (p0 < NPIX) bv = *(const float4*)&Hb[(size_t)(k0 + b_kk) * NPIX + p0];
        __syncthreads();
        As[a_kq + 0][a_co] = av.x;
        As[a_kq + 1][a_co] = av.y;
        As[a_kq + 2][a_co] = av.z;
        As[a_kq + 3][a_co] = av.w;
        *(float4*)&Bs[b_kk][b_p0] = bv;
        __syncthreads();
#pragma unroll
        for (int kk = 0; kk < 16; kk++) {
            float4 aa = *(const float4*)&As[kk][tm * 4];
            float4 bb = *(const float4*)&Bs[kk][tn * 4];
            float aarr[4] = {aa.x, aa.y, aa.z, aa.w};
            float barr[4] = {bb.x, bb.y, bb.z, bb.w};
#pragma unroll
            for (int u = 0; u < 4; u++)
#pragma unroll
                for (int v = 0; v < 4; v++)
                    acc[u][v] = fmaf(aarr[u], barr[v], acc[u][v]);
        }
    }
    float* outbase = mode ? g_locs : g_scores;
#pragma unroll
    for (int u = 0; u < 4; u++) {
        int co = m0 + tm * 4 + u;
        if (co >= M) continue;
        float bb = bias[co];
        float* orow = outbase + ((size_t)bz * M + co) * NPIX;
#pragma unroll
        for (int v = 0; v < 4; v++) {
            int p = n0 + tn * 4 + v;
            if (p < NPIX) orow[p] = acc[u][v] + bb;
        }
    }
}

// ---------------- decode boxes, softmax fg, keys ----------------
__global__ void decode_kernel(float* __restrict__ out)
{
    int idx = blockIdx.x * blockDim.x + threadIdx.x;
    if (idx >= 2 * NANCH) return;
    int b = idx / NANCH;
    int pa = idx - b * NANCH;
    int p = pa / NA;
    int a = pa - p * NA;

    const float* sc = g_scores + (size_t)b * 70 * NPIX;
    float x0 = sc[(a * 2 + 0) * NPIX + p];
    float x1 = sc[(a * 2 + 1) * NPIX + p];
    size_t so = OFF_SCORES + (size_t)b * 175000 + (size_t)pa * 2;
    out[so + 0] = x0;
    out[so + 1] = x1;
    float mx = fmaxf(x0, x1);
    float e0 = expf(x0 - mx), e1 = expf(x1 - mx);
    float fg = e1 / (e0 + e1);

    const float* lc = g_locs + (size_t)b * 140 * NPIX;
    float dy  = lc[(a * 4 + 0) * NPIX + p];
    float dx_ = lc[(a * 4 + 1) * NPIX + p];
    float dh  = lc[(a * 4 + 2) * NPIX + p];
    float dw  = lc[(a * 4 + 3) * NPIX + p];
    size_t lo = OFF_LOCS + (size_t)b * 350000 + (size_t)pa * 4;
    out[lo + 0] = dy; out[lo + 1] = dx_; out[lo + 2] = dh; out[lo + 3] = dw;

    float4 an = g_anchors[pa];
    float ah = an.z - an.x, aw = an.w - an.y;
    float acy = an.x + 0.5f * ah, acx = an.y + 0.5f * aw;
    float cy = dy * ah + acy, cx = dx_ * aw + acx;
    float hh = expf(dh) * ah, ww = expf(dw) * aw;
    float y1 = cy - 0.5f * hh, x1b = cx - 0.5f * ww;
    float y2 = cy + 0.5f * hh, x2b = cx + 0.5f * ww;
    y1 = fminf(fmaxf(y1, 0.f), 800.f);
    x1b = fminf(fmaxf(x1b, 0.f), 800.f);
    y2 = fminf(fmaxf(y2, 0.f), 800.f);
    x2b = fminf(fmaxf(x2b, 0.f), 800.f);
    float hs = y2 - y1, ws = x2b - x1b;
    bool valid = (hs >= 16.f) && (ws >= 16.f);
    float s = valid ? fg : -__int_as_float(0x7f800000);

    u32 sb = __float_as_uint(s);
    u32 mm = (sb & 0x80000000u) ? ~sb : (sb | 0x80000000u);
    u64 key = ((u64)(~mm) << 32) | (u32)pa;   // ascending key = best first
    g_keys[idx] = key;
    g_boxes[idx] = make_float4(y1, x1b, y2, x2b);
}

// ---------------- zero counters + valid bits + histograms ----------------
__global__ void zero_kernel()
{
    int idx = blockIdx.x * blockDim.x + threadIdx.x;
    if (idx < 2) g_cnt[idx] = 0;
    if (idx < 2 * NW) g_validb[idx] = 0ull;
    if (idx < 2 * 65536) { g_hist1[idx] = 0; g_hist2[idx] = 0; }
}

// ---------------- histogram pass (16-bit digits, warp-aggregated atomics) ----------------
// NOTE: pass 0 must count ALL bins including the -inf bin (0xFF80) — batches can
// have < PRE_NMS valid boxes, putting rank 5999 inside the -inf bin (R4 lesson).
__global__ void hist_kernel(int pass)
{
    int idx = blockIdx.x * blockDim.x + threadIdx.x;
    int lane = threadIdx.x & 31;
    bool ok = (idx < 2 * NANCH);
    int b = 0;
    u32 bin = 0;
    if (ok) {
        b = idx / NANCH;
        u64 k = g_keys[idx];
        if (pass == 0) {
            bin = (u32)(k >> 48);
        } else {
            if ((u32)(k >> 48) == g_prefix[b]) bin = (u32)((k >> 32) & 0xffffu);
            else ok = false;
        }
    }
    unsigned act = __ballot_sync(0xffffffffu, ok);
    if (ok) {
        u32 tag = (u32)b << 16 | bin;
        unsigned grp = __match_any_sync(act, tag);
        int leader = __ffs(grp) - 1;
        if (lane == leader) {
            u32* h = pass == 0 ? g_hist1 : g_hist2;
            atomicAdd(&h[b * 65536 + bin], (u32)__popc(grp));
        }
    }
}

// ---------------- scan 65536 bins, locate rank ----------------
__global__ void scan_kernel(int pass)
{
    int b = blockIdx.x;
    int tid = threadIdx.x;  // 1024
    const u32* base = (pass == 0 ? g_hist1 : g_hist2) + b * 65536;
    __shared__ u32 ssum[1024];
    u32 local = 0;
#pragma unroll 8
    for (int j = 0; j < 64; j++) local += base[tid * 64 + j];
    ssum[tid] = local;
    __syncthreads();
    for (int off = 1; off < 1024; off <<= 1) {
        u32 v = (tid >= off) ? ssum[tid - off] : 0;
        __syncthreads();
        ssum[tid] += v;
        __syncthreads();
    }
    u32 incl = ssum[tid];
    u32 excl = incl - local;
    u32 rank = (pass == 0) ? (PRE_NMS - 1) : g_rank[b];
    if (excl <= rank && rank < incl) {
        u32 run = excl;
        for (int j = 0; j < 64; j++) {
            u32 c = base[tid * 64 + j];
            if (run + c > rank) {
                u32 digit = (u32)(tid * 64 + j);
                g_rank[b] = rank - run;
                if (pass == 0) g_prefix[b] = digit;
                else g_thresh[b] = (g_prefix[b] << 16) | digit;
                break;
            }
            run += c;
        }
    }
}

// ---------------- compact keys with score32 <= thresh (warp-aggregated, per-batch) ----------------
__global__ void compact_kernel()
{
    int idx = blockIdx.x * blockDim.x + threadIdx.x;
    int lane = threadIdx.x & 31;
    bool ok = false;
    int b = 0;
    u64 k = 0;
    if (idx < 2 * NANCH) {
        b = idx / NANCH;
        k = g_keys[idx];
        ok = ((u32)(k >> 32) <= g_thresh[b]);
    }
#pragma unroll
    for (int bb = 0; bb < 2; bb++) {
        unsigned m = __ballot_sync(0xffffffffu, ok && b == bb);
        if (m) {
            int leader = __ffs(m) - 1;
            int base = 0;
            if (lane == leader) base = atomicAdd(&g_cnt[bb], __popc(m));
            base = __shfl_sync(0xffffffffu, base, leader);
            if (ok && b == bb) {
                int pos = base + __popc(m & ((1u << lane) - 1));
                if (pos < TOPCAP) g_top[(size_t)bb * TOPCAP + pos] = k;
            }
        }
    }
}

// ---------------- bitonic sort 8192 per batch ----------------
__global__ void sort_kernel()
{
    extern __shared__ u64 s[];
    int b = blockIdx.x;
    int tid = threadIdx.x;
    int cnt = g_cnt[b];
    if (cnt > TOPCAP) cnt = TOPCAP;
    for (int i = tid; i < TOPCAP; i += 1024)
        s[i] = (i < cnt) ? g_top[(size_t)b * TOPCAP + i] : ~0ull;
    __syncthreads();
    for (int k = 2; k <= TOPCAP; k <<= 1) {
        for (int j = k >> 1; j > 0; j >>= 1) {
            for (int t = tid; t < TOPCAP; t += 1024) {
                int ixj = t ^ j;
                if (ixj > t) {
                    bool up = ((t & k) == 0);
                    u64 x = s[t], y = s[ixj];
                    if ((x > y) == up) { s[t] = y; s[ixj] = x; }
                }
            }
            __syncthreads();
        }
    }
    for (int i = tid; i < PRE_NMS; i += 1024)
        g_top[(size_t)b * TOPCAP + i] = s[i];
}

// ---------------- gather sorted boxes + valid bits (per-thread atomicOr; 6000 % 32 != 0
// makes ballot aggregation across the batch boundary unsafe — R4 lesson) ----------------
__global__ void gather_kernel()
{
    int idx = blockIdx.x * blockDim.x + threadIdx.x;
    if (idx >= 2 * PRE_NMS) return;
    int b = idx / PRE_NMS;
    int j = idx - b * PRE_NMS;
    u64 k = g_top[(size_t)b * TOPCAP + j];
    u32 ai = (u32)(k & 0xffffffffull);
    g_nmsbox[idx] = g_boxes[(size_t)b * NANCH + ai];
    bool valid = ((u32)(k >> 32)) != 0xFF800000u;
    if (valid) atomicOr(&g_validb[b * NW + (j >> 6)], 1ull << (j & 63));
}

// ---------------- NMS IoU bitmask ----------------
__global__ void nms_mask_kernel()
{
    int cb = blockIdx.x, rb = blockIdx.y, b = blockIdx.z;
    int tid = threadIdx.x;
    __shared__ float4 cbox[64];
    int j = cb * 64 + tid;
    cbox[tid] = (j < PRE_NMS) ? g_nmsbox[(size_t)b * PRE_NMS + j]
                              : make_float4(0.f, 0.f, 0.f, 0.f);
    __syncthreads();
    int i = rb * 64 + tid;
    if (i >= PRE_NMS) return;
    float4 rr = g_nmsbox[(size_t)b * PRE_NMS + i];
    float areai = (rr.z - rr.x) * (rr.w - rr.y);
    u64 bits = 0ull;
#pragma unroll 4
    for (int c = 0; c < 64; c++) {
        int jj = cb * 64 + c;
        if (jj <= i || jj >= PRE_NMS) continue;
        float4 cc = cbox[c];
        float ty = fmaxf(rr.x, cc.x), tx = fmaxf(rr.y, cc.y);
        float by = fminf(rr.z, cc.z), bx2 = fminf(rr.w, cc.w);
        float wy = fmaxf(by - ty, 0.f), wx = fmaxf(bx2 - tx, 0.f);
        float inter = wy * wx;
        float areaj = (cc.z - cc.x) * (cc.w - cc.y);
        float iou = inter / (areai + areaj - inter + 1e-9f);
        if (iou > 0.7f) bits |= 1ull << c;
    }
    g_mask[((size_t)b * PRE_NMS + i) * NW + cb] = bits;
}

// ---------------- NMS sequential reduction: smem-chunked, cp.async double-buffered ----------------
__device__ __forceinline__ u32 smem_addr_of(const void* p)
{
    return (u32)__cvta_generic_to_shared(p);
}

__global__ void __launch_bounds__(256)
nms_reduce2_kernel()
{
    int b = blockIdx.x;
    int tid = threadIdx.x;
    extern __shared__ u64 sbuf[];   // [2][64][NW]
    __shared__ u64 remv[NW];
    __shared__ u64 svalid[NW];
    __shared__ u64 skeep;
    for (int v = tid; v < NW; v += 256) {
        remv[v] = 0ull;
        svalid[v] = g_validb[b * NW + v];
    }
    __syncthreads();

    auto issue_chunk = [&](int w, int buf) {
        int rows = PRE_NMS - w * 64;
        if (rows > 64) rows = 64;
        int total = rows * 47;
        const u64* gbase = g_mask + ((size_t)b * PRE_NMS + (size_t)w * 64) * NW;
        u64* sb0 = sbuf + (size_t)buf * 64 * NW;
        for (int e = tid; e < total; e += 256) {
            int r = e / 47, sg = e - r * 47;
            const u64* gp = gbase + (size_t)r * NW + sg * 2;
            u32 sa = smem_addr_of(sb0 + r * NW + sg * 2);
            asm volatile("cp.async.cg.shared.global [%0], [%1], 16;\n" :: "r"(sa), "l"(gp));
        }
        asm volatile("cp.async.commit_group;\n" ::);
    };

    issue_chunk(0, 0);
    for (int w = 0; w < NW; w++) {
        int buf = w & 1;
        if (w + 1 < NW) {
            issue_chunk(w + 1, buf ^ 1);
            asm volatile("cp.async.wait_group 1;\n" ::);
        } else {
            asm volatile("cp.async.wait_group 0;\n" ::);
        }
        __syncthreads();
        const u64* rowb = sbuf + (size_t)buf * 64 * NW;
        if (tid == 0) {
            u64 cur = svalid[w] & ~remv[w];
            u64 kp = 0ull;
            while (cur) {
                int bit = __ffsll((long long)cur) - 1;
                kp |= (1ull << bit);
                cur &= ~rowb[bit * NW + w];
                cur &= ~(1ull << bit);
            }
            skeep = kp;
            g_keepw[b * NW + w] = kp;
        }
        __syncthreads();
        u64 kp = skeep;
        for (int v = w + 1 + tid; v < NW; v += 256) {
            u64 acc = remv[v];
            u64 t = kp;
            while (t) {
                int bit = __ffsll((long long)t) - 1;
                t &= t - 1;
                acc |= rowb[bit * NW + v];
            }
            remv[v] = acc;
        }
        __syncthreads();
    }
}

// ---------------- finalize rois / roi_indices / roi_valid ----------------
__global__ void finalize_kernel(float* __restrict__ out)
{
    int b = blockIdx.x;
    int tid = threadIdx.x;   // 128 threads
    __shared__ u64 kw[NW];
    __shared__ u32 kscan[NW];
    __shared__ u32 ktot;
    __shared__ int sel[POST_NMS];
    for (int w = tid; w < NW; w += 128) kw[w] = g_keepw[b * NW + w];
    __syncthreads();
    if (tid == 0) {
        u32 r = 0;
        for (int w = 0; w < NW; w++) { kscan[w] = r; r += (u32)__popcll(kw[w]); }
        ktot = r;
    }
    __syncthreads();
    u32 ktot_l = ktot;
    for (int w = tid; w < NW; w += 128) {
        u64 bits = kw[w];
        u32 base = kscan[w];
        u64 t = bits;
        while (t) {
            int bit = __ffsll((long long)t) - 1;
            t &= t - 1;
            if (base < POST_NMS) sel[base] = w * 64 + bit;
            base++;
        }
        u64 lim = (w == NW - 1) ? ((1ull << 48) - 1ull) : ~0ull;  // 6000 = 93*64+48
        u64 nt = (~bits) & lim;
        while (nt) {
            int bit = __ffsll((long long)nt) - 1;
            nt &= nt - 1;
            int i = w * 64 + bit;
            u64 below = (bit == 0) ? 0ull : ((1ull << bit) - 1ull);
            u32 kept_before = kscan[w] + (u32)__popcll(bits & below);
            u32 slot = ktot_l + (u32)i - kept_before;
            if (slot < POST_NMS) sel[slot] = i;
        }
    }
    __syncthreads();
    for (int s2 = tid; s2 < POST_NMS; s2 += 128) {
        int i = sel[s2];
        int v = (int)((kw[i >> 6] >> (i & 63)) & 1ull);
        float4 bx = v ? g_nmsbox[(size_t)b * PRE_NMS + i] : make_float4(0.f, 0.f, 0.f, 0.f);
        size_t ro = OFF_ROIS + (size_t)b * POST_NMS * 4 + (size_t)s2 * 4;
        out[ro + 0] = bx.x; out[ro + 1] = bx.y; out[ro + 2] = bx.z; out[ro + 3] = bx.w;
        out[OFF_RIDX + (size_t)b * POST_NMS + s2] = (float)b;
        out[OFF_RVALID + (size_t)b * POST_NMS + s2] = (float)v;
    }
}

// ---------------- launch ----------------
extern "C" void kernel_launch(void* const* d_in, const int* in_sizes, int n_in,
                              void* d_out, int out_size)
{
    const float* feat   = (const float*)d_in[0];
    const float* convw  = (const float*)d_in[1];
    const float* convb  = (const float*)d_in[2];
    const float* scorew = (const float*)d_in[3];
    const float* scoreb = (const float*)d_in[4];
    const float* locw   = (const float*)d_in[5];
    const float* locb   = (const float*)d_in[6];
    float* out = (float*)d_out;

    cudaFuncSetAttribute(sort_kernel, cudaFuncAttributeMaxDynamicSharedMemorySize, 65536);
    cudaFuncSetAttribute(nms_reduce2_kernel, cudaFuncAttributeMaxDynamicSharedMemorySize, 2 * 64 * NW * 8);

    // ncu captures our launch index 3 -> conv3x3 there
    pad_kernel<<<(2 * NCH * QPAD + 255) / 256, 256>>>(feat);                 // 0
    zero_kernel<<<(2 * 65536 + 255) / 256, 256>>>();                         // 1
    anchors_kernel<<<(NANCH + 127) / 128, 128>>>(out);                       // 2
    conv3x3_kernel<<<dim3(32, 4, 2), 256>>>(convw, convb);                   // 3  <- profiled
    gemm1x1_kernel<<<dim3(40, 2, 2), 256>>>(scorew, scoreb, 70, 0);          // 4
    gemm1x1_kernel<<<dim3(40, 3, 2), 256>>>(locw, locb, 140, 1);             // 5
    decode_kernel<<<(2 * NANCH + 255) / 256, 256>>>(out);                    // 6
    hist_kernel<<<(2 * NANCH + 255) / 256, 256>>>(0);                        // 7
    scan_kernel<<<2, 1024>>>(0);                                             // 8
    hist_kernel<<<(2 * NANCH + 255) / 256, 256>>>(1);                        // 9
    scan_kernel<<<2, 1024>>>(1);                                             // 10
    compact_kernel<<<(2 * NANCH + 255) / 256, 256>>>();                      // 11
    sort_kernel<<<2, 1024, 65536>>>();                                       // 12
    gather_kernel<<<(2 * PRE_NMS + 255) / 256, 256>>>();                     // 13
    nms_mask_kernel<<<dim3(NW, NW, 2), 64>>>();                              // 14
    nms_reduce2_kernel<<<2, 256, 2 * 64 * NW * 8>>>();                       // 15
    finalize_kernel<<<2, 128>>>(out);                                        // 16
}

// round 7
// speedup vs baseline: 1.8644x; 1.0580x over previous
#include <cuda_runtime.h>
#include <cuda_bf16.h>
#include <math.h>

typedef unsigned int u32;
typedef unsigned long long u64;

// ---------------- problem constants ----------------
#define NPIX    2500
#define HPAD    52
#define QPAD    2704          // 52*52
#define NCH     512
#define KTOT    4608          // 512*9
#define NA      35
#define NANCH   87500         // 2500*35
#define PRE_NMS 6000
#define POST_NMS 300
#define NW      94            // ceil(6000/64)
#define TOPCAP  8192

// output layout (float32, concatenated tuple)
#define OFF_LOCS    0
#define OFF_SCORES  700000
#define OFF_ROIS    1050000
#define OFF_RIDX    1052400
#define OFF_RVALID  1053000
#define OFF_ANCH    1053600

// ---------------- device scratch (no allocation allowed) ----------------
__device__ __align__(16) float g_pad[2 * NCH * QPAD];
__device__ __align__(16) float g_h[2 * NCH * NPIX];
__device__ __align__(16) float g_scores[2 * 70 * NPIX];
__device__ __align__(16) float g_locs[2 * 140 * NPIX];
__device__ float4 g_anchors2[NANCH];     // a-major: [a][p]
__device__ u64    g_keys[2 * NANCH];
__device__ float4 g_boxes[2 * NANCH];
__device__ int    g_cnt[2];
__device__ u64    g_top[2 * TOPCAP];
__device__ float4 g_nmsbox[2 * PRE_NMS];
__device__ u64    g_mask[(size_t)2 * PRE_NMS * NW];
__device__ u64    g_validb[2 * NW];
__device__ u64    g_keepw[2 * NW];
__device__ u32    g_hist1[2 * 65536];
__device__ u32    g_hist2[2 * 65536];
__device__ u32    g_prefix[2];
__device__ u32    g_rank[2];
__device__ u32    g_thresh[2];

// ---------------- pad input (zero border) ----------------
__global__ void pad_kernel(const float* __restrict__ feat)
{
    int idx = blockIdx.x * blockDim.x + threadIdx.x;
    if (idx >= 2 * NCH * QPAD) return;
    int plane = idx / QPAD;
    int q = idx - plane * QPAD;
    int i = q / HPAD, j = q - i * HPAD;
    float v = 0.f;
    if (i >= 1 && i <= 50 && j >= 1 && j <= 50)
        v = feat[(size_t)plane * NPIX + (i - 1) * 50 + (j - 1)];
    g_pad[idx] = v;
}

// ---------------- zero counters + valid bits + histograms ----------------
__global__ void zero_kernel()
{
    int idx = blockIdx.x * blockDim.x + threadIdx.x;
    if (idx < 2) g_cnt[idx] = 0;
    if (idx < 2 * NW) g_validb[idx] = 0ull;
    if (idx < 2 * 65536) { g_hist1[idx] = 0; g_hist2[idx] = 0; }
}

// ---------------- anchors (fp64 base, fp32 add, clip) ----------------
__global__ void anchors_kernel(float* __restrict__ out)
{
    int idx = blockIdx.x * blockDim.x + threadIdx.x;
    if (idx >= NANCH) return;
    int p = idx / NA, a = idx - p * NA;
    int ri = a / 5, si = a - ri * 5;
    const double RAT[7] = {0.5, 0.66, 0.75, 1.0, 1.33, 1.5, 2.0};
    const double SCL[5] = {2.0, 4.0, 8.0, 16.0, 32.0};
    double hh = 16.0 * SCL[si] * sqrt(RAT[ri]);
    double ww = 16.0 * SCL[si] * sqrt(1.0 / RAT[ri]);
    float a0 = (float)(8.0 - hh / 2.0);
    float a1 = (float)(8.0 - ww / 2.0);
    float a2 = (float)(8.0 + hh / 2.0);
    float a3 = (float)(8.0 + ww / 2.0);
    int iy = p / 50, jx = p - iy * 50;
    float sy = (float)(iy * 16), sx = (float)(jx * 16);
    float y1 = fminf(fmaxf(a0 + sy, 0.f), 799.f);
    float x1 = fminf(fmaxf(a1 + sx, 0.f), 799.f);
    float y2 = fminf(fmaxf(a2 + sy, 0.f), 799.f);
    float x2 = fminf(fmaxf(a3 + sx, 0.f), 799.f);
    g_anchors2[a * NPIX + p] = make_float4(y1, x1, y2, x2);
    size_t o = OFF_ANCH + (size_t)idx * 4;
    out[o + 0] = y1; out[o + 1] = x1; out[o + 2] = y2; out[o + 3] = x2;
}

// ---------------- conv3x3 + bias + relu as implicit GEMM, double-buffered ----------------
// tile 128co x 80pix, 256 threads, 8x5 micro-tile, KB=8
// grid = 32 pix-tiles x 4 co-tiles x 2 batch = 256 blocks (occ-2 single wave)
#define PTILE 80
__global__ void __launch_bounds__(256, 2)
conv3x3_kernel(const float* __restrict__ W, const float* __restrict__ bias)
{
    const int bx = blockIdx.x;
    const int by = blockIdx.y;
    const int bz = blockIdx.z;
    const int tid = threadIdx.x;
    const int n0 = bx * PTILE;
    const int m0 = by * 128;
    __shared__ __align__(16) float As[2][8][128];
    __shared__ __align__(16) float Bs[2][8][PTILE];
    const int tm = tid >> 4;
    const int tn = tid & 15;
    float acc[8][5];
#pragma unroll
    for (int u = 0; u < 8; u++)
#pragma unroll
        for (int v = 0; v < 5; v++) acc[u][v] = 0.f;

    const int a_co = tid >> 1;
    const int a_kq = (tid & 1) * 4;
    const int b_kk = tid >> 5;
    const int b_px = tid & 31;
    const float* padB = g_pad + (size_t)bz * NCH * QPAD;
    const float* wrow = W + (size_t)(m0 + a_co) * KTOT + a_kq;

    // precompute pixel bases for the 3 B sub-loads
    int poff[3];
    bool pok[3];
#pragma unroll
    for (int e = 0; e < 3; e++) {
        int px = b_px + e * 32;
        int p = n0 + px;
        pok[e] = (px < PTILE) && (p < NPIX);
        int i = pok[e] ? (p / 50) : 0;
        int j = pok[e] ? (p - 50 * i) : 0;
        poff[e] = i * HPAD + j;
    }

    float4 av;
    float bv[3];
    // prologue load k0=0
    {
        av = *(const float4*)&wrow[0];
        int k = b_kk;
        int ci = k / 9;
        int r = k - ci * 9;
        int dy = r / 3, dx = r - dy * 3;
        const float* pp = padB + (size_t)ci * QPAD + dy * HPAD + dx;
#pragma unroll
        for (int e = 0; e < 3; e++) bv[e] = pok[e] ? pp[poff[e]] : 0.f;
    }
    // store buf 0
    As[0][a_kq + 0][a_co] = av.x;
    As[0][a_kq + 1][a_co] = av.y;
    As[0][a_kq + 2][a_co] = av.z;
    As[0][a_kq + 3][a_co] = av.w;
#pragma unroll
    for (int e = 0; e < 3; e++) {
        int px = b_px + e * 32;
        if (px < PTILE) Bs[0][b_kk][px] = bv[e];
    }
    __syncthreads();

    for (int k0 = 0; k0 < KTOT; k0 += 8) {
        int buf = (k0 >> 3) & 1;
        bool more = (k0 + 8 < KTOT);
        if (more) {
            av = *(const float4*)&wrow[k0 + 8];
            int k = k0 + 8 + b_kk;
            int ci = k / 9;
            int r = k - ci * 9;
            int dy = r / 3, dx = r - dy * 3;
            const float* pp = padB + (size_t)ci * QPAD + dy * HPAD + dx;
#pragma unroll
            for (int e = 0; e < 3; e++) bv[e] = pok[e] ? pp[poff[e]] : 0.f;
        }
#pragma unroll
        for (int kk = 0; kk < 8; kk++) {
            float4 aa0 = *(const float4*)&As[buf][kk][tm * 8];
            float4 aa1 = *(const float4*)&As[buf][kk][tm * 8 + 4];
            float aarr[8] = {aa0.x, aa0.y, aa0.z, aa0.w, aa1.x, aa1.y, aa1.z, aa1.w};
            float barr[5];
#pragma unroll
            for (int v = 0; v < 5; v++) barr[v] = Bs[buf][kk][tn * 5 + v];
#pragma unroll
            for (int u = 0; u < 8; u++)
#pragma unroll
                for (int v = 0; v < 5; v++)
                    acc[u][v] = fmaf(aarr[u], barr[v], acc[u][v]);
        }
        if (more) {
            int nb = buf ^ 1;
            As[nb][a_kq + 0][a_co] = av.x;
            As[nb][a_kq + 1][a_co] = av.y;
            As[nb][a_kq + 2][a_co] = av.z;
            As[nb][a_kq + 3][a_co] = av.w;
#pragma unroll
            for (int e = 0; e < 3; e++) {
                int px = b_px + e * 32;
                if (px < PTILE) Bs[nb][b_kk][px] = bv[e];
            }
            __syncthreads();
        }
    }
#pragma unroll
    for (int u = 0; u < 8; u++) {
        int co = m0 + tm * 8 + u;
        float bb = bias[co];
        float* outrow = g_h + ((size_t)bz * NCH + co) * NPIX;
#pragma unroll
        for (int v = 0; v < 5; v++) {
            int p = n0 + tn * 5 + v;
            if (p < NPIX) outrow[p] = fmaxf(acc[u][v] + bb, 0.f);
        }
    }
}

// ---------------- 1x1 conv GEMM (scores + locs merged) ----------------
__global__ void __launch_bounds__(256)
gemm1x1_kernel(const float* __restrict__ scorew, const float* __restrict__ scoreb,
               const float* __restrict__ locw, const float* __restrict__ locb)
{
    const int bx = blockIdx.x;
    const int byr = blockIdx.y;          // 0..4: 0-1 scores, 2-4 locs
    const int bz = blockIdx.z;
    const int tid = threadIdx.x;
    const float* W;
    const float* bias;
    float* outbase;
    int M, m0;
    if (byr < 2) { W = scorew; bias = scoreb; outbase = g_scores; M = 70; m0 = byr * 64; }
    else         { W = locw;   bias = locb;   outbase = g_locs;   M = 140; m0 = (byr - 2) * 64; }
    const int n0 = bx * 64;
    __shared__ __align__(16) float As[16][64];
    __shared__ __align__(16) float Bs[16][64];
    const int tm = tid >> 4, tn = tid & 15;
    float acc[4][4];
#pragma unroll
    for (int u = 0; u < 4; u++)
#pragma unroll
        for (int v = 0; v < 4; v++) acc[u][v] = 0.f;

    const int a_co = tid >> 2;
    const int a_kq = (tid & 3) * 4;
    const int b_kk = tid >> 4;
    const int b_p0 = (tid & 15) * 4;
    const float* Hb = g_h + (size_t)bz * NCH * NPIX;

    for (int k0 = 0; k0 < NCH; k0 += 16) {
        int co = m0 + a_co;
        float4 av = make_float4(0.f, 0.f, 0.f, 0.f);
        if (co < M) av = *(const float4*)&W[(size_t)co * NCH + k0 + a_kq];
        int p0 = n0 + b_p0;
        float4 bv = make_float4(0.f, 0.f, 0.f, 0.f);
        if (p0 < NPIX) bv = *(const float4*)&Hb[(size_t)(k0 + b_kk) * NPIX + p0];
        __syncthreads();
        As[a_kq + 0][a_co] = av.x;
        As[a_kq + 1][a_co] = av.y;
        As[a_kq + 2][a_co] = av.z;
        As[a_kq + 3][a_co] = av.w;
        *(float4*)&Bs[b_kk][b_p0] = bv;
        __syncthreads();
#pragma unroll
        for (int kk = 0; kk < 16; kk++) {
            float4 aa = *(const float4*)&As[kk][tm * 4];
            float4 bb = *(const float4*)&Bs[kk][tn * 4];
            float aarr[4] = {aa.x, aa.y, aa.z, aa.w};
            float barr[4] = {bb.x, bb.y, bb.z, bb.w};
#pragma unroll
            for (int u = 0; u < 4; u++)
#pragma unroll
                for (int v = 0; v < 4; v++)
                    acc[u][v] = fmaf(aarr[u], barr[v], acc[u][v]);
        }
    }
#pragma unroll
    for (int u = 0; u < 4; u++) {
        int co = m0 + tm * 4 + u;
        if (co >= M) continue;
        float bb = bias[co];
        float* orow = outbase + ((size_t)bz * M + co) * NPIX;
#pragma unroll
        for (int v = 0; v < 4; v++) {
            int p = n0 + tn * 4 + v;
            if (p < NPIX) orow[p] = acc[u][v] + bb;
        }
    }
}

// ---------------- decode boxes, softmax fg, keys ((a,p) order: coalesced loads) ----------------
__global__ void decode_kernel(float* __restrict__ out)
{
    int t = blockIdx.x * blockDim.x + threadIdx.x;
    if (t >= 2 * NANCH) return;
    int b = t / NANCH;
    int r = t - b * NANCH;
    int a = r / NPIX;
    int p = r - a * NPIX;
    int pa = p * NA + a;

    const float* sc = g_scores + (size_t)b * 70 * NPIX;
    float x0 = sc[(a * 2 + 0) * NPIX + p];
    float x1 = sc[(a * 2 + 1) * NPIX + p];
    size_t so = OFF_SCORES + (size_t)b * 175000 + (size_t)pa * 2;
    out[so + 0] = x0;
    out[so + 1] = x1;
    float mx = fmaxf(x0, x1);
    float e0 = expf(x0 - mx), e1 = expf(x1 - mx);
    float fg = e1 / (e0 + e1);

    const float* lc = g_locs + (size_t)b * 140 * NPIX;
    float dy  = lc[(a * 4 + 0) * NPIX + p];
    float dx_ = lc[(a * 4 + 1) * NPIX + p];
    float dh  = lc[(a * 4 + 2) * NPIX + p];
    float dw  = lc[(a * 4 + 3) * NPIX + p];
    size_t lo = OFF_LOCS + (size_t)b * 350000 + (size_t)pa * 4;
    out[lo + 0] = dy; out[lo + 1] = dx_; out[lo + 2] = dh; out[lo + 3] = dw;

    float4 an = g_anchors2[a * NPIX + p];
    float ah = an.z - an.x, aw = an.w - an.y;
    float acy = an.x + 0.5f * ah, acx = an.y + 0.5f * aw;
    float cy = dy * ah + acy, cx = dx_ * aw + acx;
    float hh = expf(dh) * ah, ww = expf(dw) * aw;
    float y1 = cy - 0.5f * hh, x1b = cx - 0.5f * ww;
    float y2 = cy + 0.5f * hh, x2b = cx + 0.5f * ww;
    y1 = fminf(fmaxf(y1, 0.f), 800.f);
    x1b = fminf(fmaxf(x1b, 0.f), 800.f);
    y2 = fminf(fmaxf(y2, 0.f), 800.f);
    x2b = fminf(fmaxf(x2b, 0.f), 800.f);
    float hs = y2 - y1, ws = x2b - x1b;
    bool valid = (hs >= 16.f) && (ws >= 16.f);
    float s = valid ? fg : -__int_as_float(0x7f800000);

    u32 sb = __float_as_uint(s);
    u32 mm = (sb & 0x80000000u) ? ~sb : (sb | 0x80000000u);
    u64 key = ((u64)(~mm) << 32) | (u32)pa;   // ascending key = best first
    g_keys[(size_t)b * NANCH + pa] = key;
    g_boxes[(size_t)b * NANCH + pa] = make_float4(y1, x1b, y2, x2b);
}

// ---------------- histogram pass (16-bit digits, warp-aggregated atomics) ----------------
// pass 0 counts ALL bins; the hot -inf bin (0xFF80) is accumulated in smem and
// flushed once per block (same exact counts, no hot-address serialization).
__global__ void hist_kernel(int pass)
{
    __shared__ int sneg[2];
    if (threadIdx.x < 2) sneg[threadIdx.x] = 0;
    __syncthreads();
    int idx = blockIdx.x * blockDim.x + threadIdx.x;
    int lane = threadIdx.x & 31;
    bool ok = (idx < 2 * NANCH);
    int b = 0;
    u32 bin = 0;
    if (ok) {
        b = idx / NANCH;
        u64 k = g_keys[idx];
        if (pass == 0) {
            bin = (u32)(k >> 48);
        } else {
            if ((u32)(k >> 48) == g_prefix[b]) bin = (u32)((k >> 32) & 0xffffu);
            else ok = false;
        }
    }
    unsigned act = __ballot_sync(0xffffffffu, ok);
    if (ok) {
        u32 tag = (u32)b << 16 | bin;
        unsigned grp = __match_any_sync(act, tag);
        int leader = __ffs(grp) - 1;
        if (lane == leader) {
            if (pass == 0 && bin == 0xFF80u)
                atomicAdd(&sneg[b], (int)__popc(grp));
            else {
                u32* h = pass == 0 ? g_hist1 : g_hist2;
                atomicAdd(&h[b * 65536 + bin], (u32)__popc(grp));
            }
        }
    }
    __syncthreads();
    if (pass == 0 && threadIdx.x < 2 && sneg[threadIdx.x] > 0)
        atomicAdd(&g_hist1[threadIdx.x * 65536 + 0xFF80], (u32)sneg[threadIdx.x]);
}

// ---------------- scan 65536 bins, locate rank ----------------
__global__ void scan_kernel(int pass)
{
    int b = blockIdx.x;
    int tid = threadIdx.x;  // 1024
    const u32* base = (pass == 0 ? g_hist1 : g_hist2) + b * 65536;
    __shared__ u32 ssum[1024];
    u32 local = 0;
#pragma unroll 8
    for (int j = 0; j < 64; j++) local += base[tid * 64 + j];
    ssum[tid] = local;
    __syncthreads();
    for (int off = 1; off < 1024; off <<= 1) {
        u32 v = (tid >= off) ? ssum[tid - off] : 0;
        __syncthreads();
        ssum[tid] += v;
        __syncthreads();
    }
    u32 incl = ssum[tid];
    u32 excl = incl - local;
    u32 rank = (pass == 0) ? (PRE_NMS - 1) : g_rank[b];
    if (excl <= rank && rank < incl) {
        u32 run = excl;
        for (int j = 0; j < 64; j++) {
            u32 c = base[tid * 64 + j];
            if (run + c > rank) {
                u32 digit = (u32)(tid * 64 + j);
                g_rank[b] = rank - run;
                if (pass == 0) g_prefix[b] = digit;
                else g_thresh[b] = (g_prefix[b] << 16) | digit;
                break;
            }
            run += c;
        }
    }
}

// ---------------- compact keys with score32 <= thresh (warp-aggregated, per-batch) ----------------
__global__ void compact_kernel()
{
    int idx = blockIdx.x * blockDim.x + threadIdx.x;
    int lane = threadIdx.x & 31;
    bool ok = false;
    int b = 0;
    u64 k = 0;
    if (idx < 2 * NANCH) {
        b = idx / NANCH;
        k = g_keys[idx];
        ok = ((u32)(k >> 32) <= g_thresh[b]);
    }
#pragma unroll
    for (int bb = 0; bb < 2; bb++) {
        unsigned m = __ballot_sync(0xffffffffu, ok && b == bb);
        if (m) {
            int leader = __ffs(m) - 1;
            int base = 0;
            if (lane == leader) base = atomicAdd(&g_cnt[bb], __popc(m));
            base = __shfl_sync(0xffffffffu, base, leader);
            if (ok && b == bb) {
                int pos = base + __popc(m & ((1u << lane) - 1));
                if (pos < TOPCAP) g_top[(size_t)bb * TOPCAP + pos] = k;
            }
        }
    }
}

// ---------------- bitonic sort 8192 per batch ----------------
__global__ void sort_kernel()
{
    extern __shared__ u64 s[];
    int b = blockIdx.x;
    int tid = threadIdx.x;
    int cnt = g_cnt[b];
    if (cnt > TOPCAP) cnt = TOPCAP;
    for (int i = tid; i < TOPCAP; i += 1024)
        s[i] = (i < cnt) ? g_top[(size_t)b * TOPCAP + i] : ~0ull;
    __syncthreads();
    for (int k = 2; k <= TOPCAP; k <<= 1) {
        for (int j = k >> 1; j > 0; j >>= 1) {
            for (int t = tid; t < TOPCAP; t += 1024) {
                int ixj = t ^ j;
                if (ixj > t) {
                    bool up = ((t & k) == 0);
                    u64 x = s[t], y = s[ixj];
                    if ((x > y) == up) { s[t] = y; s[ixj] = x; }
                }
            }
            __syncthreads();
        }
    }
    for (int i = tid; i < PRE_NMS; i += 1024)
        g_top[(size_t)b * TOPCAP + i] = s[i];
}

// ---------------- gather sorted boxes + valid bits ----------------
__global__ void gather_kernel()
{
    int idx = blockIdx.x * blockDim.x + threadIdx.x;
    if (idx >= 2 * PRE_NMS) return;
    int b = idx / PRE_NMS;
    int j = idx - b * PRE_NMS;
    u64 k = g_top[(size_t)b * TOPCAP + j];
    u32 ai = (u32)(k & 0xffffffffull);
    g_nmsbox[idx] = g_boxes[(size_t)b * NANCH + ai];
    bool valid = ((u32)(k >> 32)) != 0xFF800000u;
    if (valid) atomicOr(&g_validb[b * NW + (j >> 6)], 1ull << (j & 63));
}

// ---------------- NMS IoU bitmask (upper triangle only; reducer never reads v<w) ----------------
__global__ void nms_mask_kernel()
{
    int cb = blockIdx.x, rb = blockIdx.y, b = blockIdx.z;
    if (cb < rb) return;
    int tid = threadIdx.x;
    __shared__ float4 cbox[64];
    int j = cb * 64 + tid;
    cbox[tid] = (j < PRE_NMS) ? g_nmsbox[(size_t)b * PRE_NMS + j]
                              : make_float4(0.f, 0.f, 0.f, 0.f);
    __syncthreads();
    int i = rb * 64 + tid;
    if (i >= PRE_NMS) return;
    float4 rr = g_nmsbox[(size_t)b * PRE_NMS + i];
    float areai = (rr.z - rr.x) * (rr.w - rr.y);
    u64 bits = 0ull;
    if (cb > rb) {
        // zero boxes (j >= PRE_NMS) give IoU 0 -> no bit; no per-element checks
#pragma unroll 4
        for (int c = 0; c < 64; c++) {
            float4 cc = cbox[c];
            float ty = fmaxf(rr.x, cc.x), tx = fmaxf(rr.y, cc.y);
            float by = fminf(rr.z, cc.z), bx2 = fminf(rr.w, cc.w);
            float wy = fmaxf(by - ty, 0.f), wx = fmaxf(bx2 - tx, 0.f);
            float inter = wy * wx;
            float areaj = (cc.z - cc.x) * (cc.w - cc.y);
            float iou = inter / (areai + areaj - inter + 1e-9f);
            if (iou > 0.7f) bits |= 1ull << c;
        }
    } else {
        for (int c = tid + 1; c < 64; c++) {
            float4 cc = cbox[c];
            float ty = fmaxf(rr.x, cc.x), tx = fmaxf(rr.y, cc.y);
            float by = fminf(rr.z, cc.z), bx2 = fminf(rr.w, cc.w);
            float wy = fmaxf(by - ty, 0.f), wx = fmaxf(bx2 - tx, 0.f);
            float inter = wy * wx;
            float areaj = (cc.z - cc.x) * (cc.w - cc.y);
            float iou = inter / (areai + areaj - inter + 1e-9f);
            if (iou > 0.7f) bits |= 1ull << c;
        }
    }
    g_mask[((size_t)b * PRE_NMS + i) * NW + cb] = bits;
}

// ---------------- NMS sequential reduction: smem-chunked, cp.async double-buffered ----------------
__device__ __forceinline__ u32 smem_addr_of(const void* p)
{
    return (u32)__cvta_generic_to_shared(p);
}

__global__ void __launch_bounds__(256)
nms_reduce2_kernel()
{
    int b = blockIdx.x;
    int tid = threadIdx.x;
    extern __shared__ u64 sbuf[];   // [2][64][NW]
    __shared__ u64 remv[NW];
    __shared__ u64 svalid[NW];
    __shared__ u64 skeep;
    for (int v = tid; v < NW; v += 256) {
        remv[v] = 0ull;
        svalid[v] = g_validb[b * NW + v];
    }
    __syncthreads();

    auto issue_chunk = [&](int w, int buf) {
        int rows = PRE_NMS - w * 64;
        if (rows > 64) rows = 64;
        int total = rows * 47;
        const u64* gbase = g_mask + ((size_t)b * PRE_NMS + (size_t)w * 64) * NW;
        u64* sb0 = sbuf + (size_t)buf * 64 * NW;
        for (int e = tid; e < total; e += 256) {
            int r = e / 47, sg = e - r * 47;
            const u64* gp = gbase + (size_t)r * NW + sg * 2;
            u32 sa = smem_addr_of(sb0 + r * NW + sg * 2);
            asm volatile("cp.async.cg.shared.global [%0], [%1], 16;\n" :: "r"(sa), "l"(gp));
        }
        asm volatile("cp.async.commit_group;\n" ::);
    };

    issue_chunk(0, 0);
    for (int w = 0; w < NW; w++) {
        int buf = w & 1;
        if (w + 1 < NW) {
            issue_chunk(w + 1, buf ^ 1);
            asm volatile("cp.async.wait_group 1;\n" ::);
        } else {
            asm volatile("cp.async.wait_group 0;\n" ::);
        }
        __syncthreads();
        const u64* rowb = sbuf + (size_t)buf * 64 * NW;
        if (tid == 0) {
            u64 cur = svalid[w] & ~remv[w];
            u64 kp = 0ull;
            while (cur) {
                int bit = __ffsll((long long)cur) - 1;
                kp |= (1ull << bit);
                cur &= ~rowb[bit * NW + w];
                cur &= ~(1ull << bit);
            }
            skeep = kp;
            g_keepw[b * NW + w] = kp;
        }
        __syncthreads();
        u64 kp = skeep;
        for (int v = w + 1 + tid; v < NW; v += 256) {
            u64 acc = remv[v];
            u64 t = kp;
            while (t) {
                int bit = __ffsll((long long)t) - 1;
                t &= t - 1;
                acc |= rowb[bit * NW + v];
            }
            remv[v] = acc;
        }
        __syncthreads();
    }
}

// ---------------- finalize rois / roi_indices / roi_valid ----------------
__global__ void finalize_kernel(float* __restrict__ out)
{
    int b = blockIdx.x;
    int tid = threadIdx.x;   // 128 threads
    __shared__ u64 kw[NW];
    __shared__ u32 kscan[NW];
    __shared__ u32 ktot;
    __shared__ int sel[POST_NMS];
    for (int w = tid; w < NW; w += 128) kw[w] = g_keepw[b * NW + w];
    __syncthreads();
    if (tid == 0) {
        u32 r = 0;
        for (int w = 0; w < NW; w++) { kscan[w] = r; r += (u32)__popcll(kw[w]); }
        ktot = r;
    }
    __syncthreads();
    u32 ktot_l = ktot;
    for (int w = tid; w < NW; w += 128) {
        u64 bits = kw[w];
        u32 base = kscan[w];
        u64 t = bits;
        while (t) {
            int bit = __ffsll((long long)t) - 1;
            t &= t - 1;
            if (base < POST_NMS) sel[base] = w * 64 + bit;
            base++;
        }
        u64 lim = (w == NW - 1) ? ((1ull << 48) - 1ull) : ~0ull;  // 6000 = 93*64+48
        u64 nt = (~bits) & lim;
        while (nt) {
            int bit = __ffsll((long long)nt) - 1;
            nt &= nt - 1;
            int i = w * 64 + bit;
            u64 below = (bit == 0) ? 0ull : ((1ull << bit) - 1ull);
            u32 kept_before = kscan[w] + (u32)__popcll(bits & below);
            u32 slot = ktot_l + (u32)i - kept_before;
            if (slot < POST_NMS) sel[slot] = i;
        }
    }
    __syncthreads();
    for (int s2 = tid; s2 < POST_NMS; s2 += 128) {
        int i = sel[s2];
        int v = (int)((kw[i >> 6] >> (i & 63)) & 1ull);
        float4 bx = v ? g_nmsbox[(size_t)b * PRE_NMS + i] : make_float4(0.f, 0.f, 0.f, 0.f);
        size_t ro = OFF_ROIS + (size_t)b * POST_NMS * 4 + (size_t)s2 * 4;
        out[ro + 0] = bx.x; out[ro + 1] = bx.y; out[ro + 2] = bx.z; out[ro + 3] = bx.w;
        out[OFF_RIDX + (size_t)b * POST_NMS + s2] = (float)b;
        out[OFF_RVALID + (size_t)b * POST_NMS + s2] = (float)v;
    }
}

// ---------------- launch ----------------
extern "C" void kernel_launch(void* const* d_in, const int* in_sizes, int n_in,
                              void* d_out, int out_size)
{
    const float* feat   = (const float*)d_in[0];
    const float* convw  = (const float*)d_in[1];
    const float* convb  = (const float*)d_in[2];
    const float* scorew = (const float*)d_in[3];
    const float* scoreb = (const float*)d_in[4];
    const float* locw   = (const float*)d_in[5];
    const float* locb   = (const float*)d_in[6];
    float* out = (float*)d_out;

    cudaFuncSetAttribute(sort_kernel, cudaFuncAttributeMaxDynamicSharedMemorySize, 65536);
    cudaFuncSetAttribute(nms_reduce2_kernel, cudaFuncAttributeMaxDynamicSharedMemorySize, 2 * 64 * NW * 8);

    // keep exactly 3 launches before conv so the ncu slot (index 3) stays on conv3x3
    pad_kernel<<<(2 * NCH * QPAD + 255) / 256, 256>>>(feat);                 // 0
    zero_kernel<<<(2 * 65536 + 255) / 256, 256>>>();                         // 1
    anchors_kernel<<<(NANCH + 127) / 128, 128>>>(out);                       // 2
    conv3x3_kernel<<<dim3(32, 4, 2), 256>>>(convw, convb);                   // 3  <- profiled
    gemm1x1_kernel<<<dim3(40, 5, 2), 256>>>(scorew, scoreb, locw, locb);     // 4
    decode_kernel<<<(2 * NANCH + 255) / 256, 256>>>(out);                    // 5
    hist_kernel<<<(2 * NANCH + 255) / 256, 256>>>(0);                        // 6
    scan_kernel<<<2, 1024>>>(0);                                             // 7
    hist_kernel<<<(2 * NANCH + 255) / 256, 256>>>(1);                        // 8
    scan_kernel<<<2, 1024>>>(1);                                             // 9
    compact_kernel<<<(2 * NANCH + 255) / 256, 256>>>();                      // 10
    sort_kernel<<<2, 1024, 65536>>>();                                       // 11
    gather_kernel<<<(2 * PRE_NMS + 255) / 256, 256>>>();                     // 12
    nms_mask_kernel<<<dim3(NW, NW, 2), 64>>>();                              // 13
    nms_reduce2_kernel<<<2, 256, 2 * 64 * NW * 8>>>();                       // 14
    finalize_kernel<<<2, 128>>>(out);                                        // 15
}